// round 6
// baseline (speedup 1.0000x reference)
#include <cuda_runtime.h>
#include <math.h>
#include <stdint.h>

// Problem constants
#define Bb   2
#define Tt   2048
#define Cc   1024
#define Hh   16
#define DHd  64
#define Mrows (Bb * Tt)          // 4096
#define QKV_N (3 * Cc)           // 3072
#define FFN_N (4 * Cc)           // 4096
#define ATT_SCALE 0.03125f       // C^-0.5 = 1/32
#define LN_EPS 1e-5f

// ---------------------------------------------------------------------------
// Scratch (static device allocations; no cudaMalloc allowed)
// ---------------------------------------------------------------------------
__device__ float g_x1  [Mrows * Cc];
__device__ float g_qkv [Mrows * QKV_N];
__device__ float g_attn[Mrows * Cc];
__device__ float g_y   [Mrows * Cc];
__device__ float g_x2  [Mrows * Cc];
__device__ float g_h   [Mrows * FFN_N];
__device__ float g_wqkv[Cc * QKV_N];      // packed [C][3C] (tf32)
__device__ float g_wo  [Cc * Cc];         // rounded [C][C]
__device__ float g_w1  [Cc * FFN_N];      // rounded [C][4C]
__device__ float g_w2  [FFN_N * Cc];      // rounded [4C][C]

// ---------------------------------------------------------------------------
// Helpers
// ---------------------------------------------------------------------------
__device__ __forceinline__ float tf32r(float x) {
    uint32_t u;
    asm("cvt.rna.tf32.f32 %0, %1;" : "=r"(u) : "f"(x));
    return __uint_as_float(u);
}
__device__ __forceinline__ void cp_async16(void* smem, const void* gmem) {
    unsigned saddr = (unsigned)__cvta_generic_to_shared(smem);
    asm volatile("cp.async.cg.shared.global [%0], [%1], 16;\n"
                 :: "r"(saddr), "l"(gmem));
}
__device__ __forceinline__ void cp_async_commit() {
    asm volatile("cp.async.commit_group;\n" ::: "memory");
}
__device__ __forceinline__ void cp_async_wait0() {
    asm volatile("cp.async.wait_group 0;\n" ::: "memory");
}
__device__ __forceinline__ void cp_async_wait1() {
    asm volatile("cp.async.wait_group 1;\n" ::: "memory");
}

__device__ __forceinline__ void mma_tf32(float c[4],
                                         const uint32_t a[4],
                                         const uint32_t b[2]) {
    asm volatile(
        "mma.sync.aligned.m16n8k8.row.col.f32.tf32.tf32.f32 "
        "{%0,%1,%2,%3}, {%4,%5,%6,%7}, {%8,%9}, {%0,%1,%2,%3};\n"
        : "+f"(c[0]), "+f"(c[1]), "+f"(c[2]), "+f"(c[3])
        : "r"(a[0]), "r"(a[1]), "r"(a[2]), "r"(a[3]),
          "r"(b[0]), "r"(b[1]));
}

// ---------------------------------------------------------------------------
// Pack Wq/Wk/Wv [H,C,DH] -> g_wqkv [C][3C] (tf32-rounded)
// ---------------------------------------------------------------------------
__global__ void pack_qkv_kernel(const float* __restrict__ Wq,
                                const float* __restrict__ Wk,
                                const float* __restrict__ Wv) {
    int idx = blockIdx.x * blockDim.x + threadIdx.x;
    if (idx >= Cc * QKV_N) return;
    int c = idx / QKV_N;
    int n = idx - c * QKV_N;
    int sel = n >> 10;
    int m = n & 1023;
    int h = m >> 6;
    int d = m & 63;
    const float* W = (sel == 0) ? Wq : (sel == 1) ? Wk : Wv;
    g_wqkv[idx] = tf32r(W[(h * Cc + c) * DHd + d]);
}

__global__ void round_kernel(const float* __restrict__ src,
                             float* __restrict__ dst, int n) {
    int i = blockIdx.x * blockDim.x + threadIdx.x;
    if (i < n) dst[i] = tf32r(src[i]);
}

// ---------------------------------------------------------------------------
// LayerNorm over axis 1 (TIME), unbiased variance. Output tf32-rounded.
// ---------------------------------------------------------------------------
__global__ __launch_bounds__(256)
void ln_axis1_kernel(const float* __restrict__ x,
                     const float* __restrict__ gamma,
                     const float* __restrict__ beta,
                     float* __restrict__ out) {
    int b  = blockIdx.y;
    int tx = threadIdx.x, ty = threadIdx.y;
    int c  = blockIdx.x * 32 + tx;
    const float* xp = x + (size_t)b * Tt * Cc + c;

    float s = 0.f, s2 = 0.f;
    for (int t = ty; t < Tt; t += 8) {
        float v = xp[(size_t)t * Cc];
        s += v; s2 += v * v;
    }
    __shared__ float ss[8][32], sq[8][32], smean[32], srstd[32];
    ss[ty][tx] = s; sq[ty][tx] = s2;
    __syncthreads();
    if (ty == 0) {
        float S = 0.f, S2 = 0.f;
#pragma unroll
        for (int k = 0; k < 8; k++) { S += ss[k][tx]; S2 += sq[k][tx]; }
        float mean = S / (float)Tt;
        float var  = (S2 - (float)Tt * mean * mean) / (float)(Tt - 1);
        smean[tx] = mean;
        srstd[tx] = rsqrtf(var + LN_EPS);
    }
    __syncthreads();
    float mean = smean[tx], rstd = srstd[tx];
    float g = gamma[c], be = beta[c];
    float* op = out + (size_t)b * Tt * Cc + c;
    for (int t = ty; t < Tt; t += 8) {
        op[(size_t)t * Cc] = tf32r(g * (xp[(size_t)t * Cc] - mean) * rstd + be);
    }
}

// ---------------------------------------------------------------------------
// TF32 mma.sync GEMM, high arithmetic intensity:
// CTA tile 256x128, BK=16, 256 threads = 8 warps (4m x 2n), warp tile 64x64.
// 3-stage cp.async pipeline. 1 CTA/SM (reg-heavy: 128 accs/thread).
// A[M][K] @ B[K][N], both tf32-pre-rounded. M%256==0, N%128==0, K%16==0.
// ---------------------------------------------------------------------------
#define ASTR 20
#define BSTR 136
#define NSTG 3
#define A_STG (256 * ASTR)
#define B_STG (16 * BSTR)
#define GEMM_SMEM ((NSTG * (A_STG + B_STG)) * (int)sizeof(float))   // 87552 B

template<bool BIAS, bool RELU, bool RES, bool ROUND>
__global__ __launch_bounds__(256, 1)
void gemm_mma_kernel(const float* __restrict__ A,
                     const float* __restrict__ Bm,
                     const float* __restrict__ bias,
                     const float* __restrict__ res,
                     float* __restrict__ Cout,
                     int M, int N, int K) {
    extern __shared__ float sm[];
    float* As = sm;                          // [NSTG][256][ASTR]
    float* Bs = sm + NSTG * A_STG;           // [NSTG][16][BSTR]

    const int tid  = threadIdx.x;
    const int lane = tid & 31;
    const int warp = tid >> 5;
    const int wm   = warp >> 1;              // 0..3
    const int wn   = warp & 1;               // 0..1
    const int gid  = lane >> 2;              // 0..7
    const int tid4 = lane & 3;               // 0..3

    const int row0 = blockIdx.y * 256;
    const int col0 = blockIdx.x * 128;
    const int nIter = K >> 4;

    float acc[4][8][4];
#pragma unroll
    for (int i = 0; i < 4; i++)
#pragma unroll
        for (int j = 0; j < 8; j++)
#pragma unroll
            for (int q = 0; q < 4; q++) acc[i][j][q] = 0.f;

    auto load_stage = [&](int s, int kc) {
        float* as = As + s * A_STG;
        float* bs = Bs + s * B_STG;
        const float* ap = A + (size_t)row0 * K + kc * 16;
#pragma unroll
        for (int q = 0; q < 4; q++) {
            int id = tid + 256 * q;
            int r = id >> 2, c4 = (id & 3) << 2;
            cp_async16(&as[r * ASTR + c4], ap + (size_t)r * K + c4);
        }
        const float* bp = Bm + (size_t)(kc * 16) * N + col0;
#pragma unroll
        for (int q = 0; q < 2; q++) {
            int id = tid + 256 * q;
            int r = id >> 5, c4 = (id & 31) << 2;
            cp_async16(&bs[r * BSTR + c4], bp + (size_t)r * N + c4);
        }
        cp_async_commit();
    };

    load_stage(0, 0);
    load_stage(1, 1);

    for (int it = 0; it < nIter; ++it) {
        cp_async_wait1();                    // stage it resident
        __syncthreads();                     // all warps done with stage it-1

        if (it + 2 < nIter) load_stage((it + 2) % NSTG, it + 2);
        else                cp_async_commit();   // keep group counts aligned

        const int s = it % NSTG;
        const float* as = As + s * A_STG;
        const float* bs = Bs + s * B_STG;

#pragma unroll
        for (int ks = 0; ks < 2; ks++) {
            const int k0 = ks * 8;
            uint32_t af[4][4];
#pragma unroll
            for (int i = 0; i < 4; i++) {
                int rb = wm * 64 + i * 16 + gid;
                af[i][0] = __float_as_uint(as[rb * ASTR + k0 + tid4]);
                af[i][1] = __float_as_uint(as[(rb + 8) * ASTR + k0 + tid4]);
                af[i][2] = __float_as_uint(as[rb * ASTR + k0 + tid4 + 4]);
                af[i][3] = __float_as_uint(as[(rb + 8) * ASTR + k0 + tid4 + 4]);
            }
            uint32_t bf[8][2];
#pragma unroll
            for (int j = 0; j < 8; j++) {
                int nb = wn * 64 + j * 8 + gid;
                bf[j][0] = __float_as_uint(bs[(k0 + tid4) * BSTR + nb]);
                bf[j][1] = __float_as_uint(bs[(k0 + tid4 + 4) * BSTR + nb]);
            }
#pragma unroll
            for (int i = 0; i < 4; i++)
#pragma unroll
                for (int j = 0; j < 8; j++)
                    mma_tf32(acc[i][j], af[i], bf[j]);
        }
    }

    // epilogue (registers only; no smem dependence)
#pragma unroll
    for (int i = 0; i < 4; i++) {
#pragma unroll
        for (int hr = 0; hr < 2; hr++) {
            int r = row0 + wm * 64 + i * 16 + hr * 8 + gid;
#pragma unroll
            for (int j = 0; j < 8; j++) {
                int cI = col0 + wn * 64 + j * 8 + 2 * tid4;
                float v0 = acc[i][j][hr * 2];
                float v1 = acc[i][j][hr * 2 + 1];
                if (BIAS) {
                    float2 bi = *(const float2*)&bias[cI];
                    v0 += bi.x; v1 += bi.y;
                }
                if (RES) {
                    float2 rv = *(const float2*)&res[(size_t)r * N + cI];
                    v0 += rv.x; v1 += rv.y;
                }
                if (RELU) { v0 = fmaxf(v0, 0.f); v1 = fmaxf(v1, 0.f); }
                if (ROUND) { v0 = tf32r(v0); v1 = tf32r(v1); }
                float2 o = make_float2(v0, v1);
                *(float2*)&Cout[(size_t)r * N + cI] = o;
            }
        }
    }
}

// ---------------------------------------------------------------------------
// Causal flash attention, tf32 mma.sync (unchanged from Round 3 PASS).
// ---------------------------------------------------------------------------
#define KSTR 68
#define VSTR 72
#define ATT_SMEM ((64*KSTR + 2*64*KSTR + 2*64*VSTR) * 4)

__global__ __launch_bounds__(128, 2)
void attn_mma_kernel(const float* __restrict__ qkv, float* __restrict__ outp) {
    extern __shared__ float sh[];
    float* Qs = sh;
    float* Ks = Qs + 64 * KSTR;
    float* Vs = Ks + 2 * 64 * KSTR;

    const int qt = blockIdx.x, h = blockIdx.y, b = blockIdx.z;
    const int t0 = qt * 64;
    const int tid  = threadIdx.x;
    const int lane = tid & 31;
    const int warp = tid >> 5;
    const int gid  = lane >> 2;
    const int tid4 = lane & 3;
    const unsigned FULL = 0xffffffffu;

    const float* base = qkv + (size_t)(b * Tt) * QKV_N + h * 64;

#pragma unroll
    for (int r = 0; r < 8; r++) {
        int id  = tid + 128 * r;
        int row = id >> 4;
        int qc  = (id & 15) * 4;
        float4 v = *(const float4*)(base + (size_t)(t0 + row) * QKV_N + qc);
        Qs[row * KSTR + qc + 0] = v.x * ATT_SCALE;
        Qs[row * KSTR + qc + 1] = v.y * ATT_SCALE;
        Qs[row * KSTR + qc + 2] = v.z * ATT_SCALE;
        Qs[row * KSTR + qc + 3] = v.w * ATT_SCALE;
    }

    {
        const float* kb = base + Cc;
        const float* vb = base + 2 * Cc;
#pragma unroll
        for (int r = 0; r < 8; r++) {
            int id  = tid + 128 * r;
            int row = id >> 4;
            int qc  = (id & 15) * 4;
            cp_async16(&Ks[row * KSTR + qc], kb + (size_t)row * QKV_N + qc);
            cp_async16(&Vs[row * VSTR + qc], vb + (size_t)row * QKV_N + qc);
        }
        cp_async_commit();
    }
    __syncthreads();

    uint32_t qa[8][4];
    {
        int rb = (16 * warp + gid) * KSTR;
#pragma unroll
        for (int k = 0; k < 8; k++) {
            qa[k][0] = __float_as_uint(Qs[rb + 8 * k + tid4]);
            qa[k][1] = __float_as_uint(Qs[rb + 8 * KSTR + 8 * k + tid4]);
            qa[k][2] = __float_as_uint(Qs[rb + 8 * k + tid4 + 4]);
            qa[k][3] = __float_as_uint(Qs[rb + 8 * KSTR + 8 * k + tid4 + 4]);
        }
    }

    float m0 = -1e30f, m1 = -1e30f, l0 = 0.f, l1 = 0.f;
    float o[8][4];
#pragma unroll
    for (int j = 0; j < 8; j++)
#pragma unroll
        for (int q = 0; q < 4; q++) o[j][q] = 0.f;

    const int nt = qt + 1;
    for (int it = 0; it < nt; ++it) {
        const int buf = it & 1;
        float* Kb = Ks + buf * 64 * KSTR;
        float* Vb = Vs + buf * 64 * VSTR;

        cp_async_wait0();
        __syncthreads();

        if (it + 1 < nt) {
            const int s0 = (it + 1) * 64;
            float* Kn = Ks + (buf ^ 1) * 64 * KSTR;
            float* Vn = Vs + (buf ^ 1) * 64 * VSTR;
            const float* kb = base + Cc     + (size_t)s0 * QKV_N;
            const float* vb = base + 2 * Cc + (size_t)s0 * QKV_N;
#pragma unroll
            for (int r = 0; r < 8; r++) {
                int id  = tid + 128 * r;
                int row = id >> 4;
                int qc  = (id & 15) * 4;
                cp_async16(&Kn[row * KSTR + qc], kb + (size_t)row * QKV_N + qc);
                cp_async16(&Vn[row * VSTR + qc], vb + (size_t)row * QKV_N + qc);
            }
            cp_async_commit();
        }

        float sc[8][4];
#pragma unroll
        for (int j = 0; j < 8; j++)
#pragma unroll
            for (int q = 0; q < 4; q++) sc[j][q] = 0.f;
#pragma unroll
        for (int k = 0; k < 8; k++) {
            uint32_t kb2[8][2];
#pragma unroll
            for (int j = 0; j < 8; j++) {
                int rb = (8 * j + gid) * KSTR + 8 * k;
                kb2[j][0] = __float_as_uint(Kb[rb + tid4]);
                kb2[j][1] = __float_as_uint(Kb[rb + tid4 + 4]);
            }
#pragma unroll
            for (int j = 0; j < 8; j++)
                mma_tf32(sc[j], qa[k], kb2[j]);
        }

        if (it == qt) {
            int r0 = 16 * warp + gid;
#pragma unroll
            for (int j = 0; j < 8; j++) {
                int c0 = 8 * j + 2 * tid4;
                if (c0     > r0)     sc[j][0] = -1e30f;
                if (c0 + 1 > r0)     sc[j][1] = -1e30f;
                if (c0     > r0 + 8) sc[j][2] = -1e30f;
                if (c0 + 1 > r0 + 8) sc[j][3] = -1e30f;
            }
        }

        float mx0 = -1e30f, mx1 = -1e30f;
#pragma unroll
        for (int j = 0; j < 8; j++) {
            mx0 = fmaxf(mx0, fmaxf(sc[j][0], sc[j][1]));
            mx1 = fmaxf(mx1, fmaxf(sc[j][2], sc[j][3]));
        }
        mx0 = fmaxf(mx0, __shfl_xor_sync(FULL, mx0, 1));
        mx0 = fmaxf(mx0, __shfl_xor_sync(FULL, mx0, 2));
        mx1 = fmaxf(mx1, __shfl_xor_sync(FULL, mx1, 1));
        mx1 = fmaxf(mx1, __shfl_xor_sync(FULL, mx1, 2));
        float mn0 = fmaxf(m0, mx0), mn1 = fmaxf(m1, mx1);
        float sum0 = 0.f, sum1 = 0.f;
#pragma unroll
        for (int j = 0; j < 8; j++) {
            sc[j][0] = __expf(sc[j][0] - mn0);
            sc[j][1] = __expf(sc[j][1] - mn0);
            sc[j][2] = __expf(sc[j][2] - mn1);
            sc[j][3] = __expf(sc[j][3] - mn1);
            sum0 += sc[j][0] + sc[j][1];
            sum1 += sc[j][2] + sc[j][3];
        }
        sum0 += __shfl_xor_sync(FULL, sum0, 1);
        sum0 += __shfl_xor_sync(FULL, sum0, 2);
        sum1 += __shfl_xor_sync(FULL, sum1, 1);
        sum1 += __shfl_xor_sync(FULL, sum1, 2);
        float c0 = __expf(m0 - mn0), c1 = __expf(m1 - mn1);
        l0 = l0 * c0 + sum0;
        l1 = l1 * c1 + sum1;
        m0 = mn0; m1 = mn1;
#pragma unroll
        for (int j = 0; j < 8; j++) {
            o[j][0] *= c0; o[j][1] *= c0;
            o[j][2] *= c1; o[j][3] *= c1;
        }

        __syncthreads();
        {
            int pr0 = (16 * warp + gid) * KSTR;
            int pr1 = pr0 + 8 * KSTR;
#pragma unroll
            for (int j = 0; j < 8; j++) {
                int cI = 8 * j + 2 * tid4;
                Kb[pr0 + cI]     = tf32r(sc[j][0]);
                Kb[pr0 + cI + 1] = tf32r(sc[j][1]);
                Kb[pr1 + cI]     = tf32r(sc[j][2]);
                Kb[pr1 + cI + 1] = tf32r(sc[j][3]);
            }
        }
        __syncwarp();

#pragma unroll
        for (int k = 0; k < 8; k++) {
            uint32_t pa[4];
            int pb = (16 * warp + gid) * KSTR + 8 * k;
            pa[0] = __float_as_uint(Kb[pb + tid4]);
            pa[1] = __float_as_uint(Kb[pb + 8 * KSTR + tid4]);
            pa[2] = __float_as_uint(Kb[pb + tid4 + 4]);
            pa[3] = __float_as_uint(Kb[pb + 8 * KSTR + tid4 + 4]);
            uint32_t vb2[8][2];
#pragma unroll
            for (int j = 0; j < 8; j++) {
                vb2[j][0] = __float_as_uint(Vb[(8 * k + tid4) * VSTR + 8 * j + gid]);
                vb2[j][1] = __float_as_uint(Vb[(8 * k + tid4 + 4) * VSTR + 8 * j + gid]);
            }
#pragma unroll
            for (int j = 0; j < 8; j++)
                mma_tf32(o[j], pa, vb2[j]);
        }
    }

    float inv0 = 1.f / l0, inv1 = 1.f / l1;
    int r0 = t0 + 16 * warp + gid;
#pragma unroll
    for (int j = 0; j < 8; j++) {
        int cI = h * 64 + 8 * j + 2 * tid4;
        float2 v0 = make_float2(tf32r(o[j][0] * inv0), tf32r(o[j][1] * inv0));
        float2 v1 = make_float2(tf32r(o[j][2] * inv1), tf32r(o[j][3] * inv1));
        *(float2*)&outp[(size_t)(b * Tt + r0) * Cc + cI]     = v0;
        *(float2*)&outp[(size_t)(b * Tt + r0 + 8) * Cc + cI] = v1;
    }
}

// ---------------------------------------------------------------------------
// Launch
// ---------------------------------------------------------------------------
extern "C" void kernel_launch(void* const* d_in, const int* in_sizes, int n_in,
                              void* d_out, int out_size) {
    const float* x      = (const float*)d_in[0];
    const float* Wq     = (const float*)d_in[1];
    const float* Wk     = (const float*)d_in[2];
    const float* Wv     = (const float*)d_in[3];
    const float* Wo     = (const float*)d_in[4];
    const float* bo     = (const float*)d_in[5];
    const float* W1     = (const float*)d_in[6];
    const float* b1     = (const float*)d_in[7];
    const float* W2     = (const float*)d_in[8];
    const float* b2     = (const float*)d_in[9];
    const float* gamma1 = (const float*)d_in[10];
    const float* beta1  = (const float*)d_in[11];
    const float* gamma2 = (const float*)d_in[12];
    const float* beta2  = (const float*)d_in[13];
    float* out = (float*)d_out;

    float *p_x1, *p_qkv, *p_attn, *p_y, *p_x2, *p_h, *p_wqkv, *p_wo, *p_w1, *p_w2;
    cudaGetSymbolAddress((void**)&p_x1,   g_x1);
    cudaGetSymbolAddress((void**)&p_qkv,  g_qkv);
    cudaGetSymbolAddress((void**)&p_attn, g_attn);
    cudaGetSymbolAddress((void**)&p_y,    g_y);
    cudaGetSymbolAddress((void**)&p_x2,   g_x2);
    cudaGetSymbolAddress((void**)&p_h,    g_h);
    cudaGetSymbolAddress((void**)&p_wqkv, g_wqkv);
    cudaGetSymbolAddress((void**)&p_wo,   g_wo);
    cudaGetSymbolAddress((void**)&p_w1,   g_w1);
    cudaGetSymbolAddress((void**)&p_w2,   g_w2);

    cudaFuncSetAttribute(gemm_mma_kernel<false, false, false, true>,
                         cudaFuncAttributeMaxDynamicSharedMemorySize, GEMM_SMEM);
    cudaFuncSetAttribute(gemm_mma_kernel<true, false, true, false>,
                         cudaFuncAttributeMaxDynamicSharedMemorySize, GEMM_SMEM);
    cudaFuncSetAttribute(gemm_mma_kernel<true, true, false, true>,
                         cudaFuncAttributeMaxDynamicSharedMemorySize, GEMM_SMEM);
    cudaFuncSetAttribute(attn_mma_kernel,
                         cudaFuncAttributeMaxDynamicSharedMemorySize, ATT_SMEM);

    // 0) weight prep: pack + tf32 round (no transposes needed; B is [K][N])
    pack_qkv_kernel<<<(Cc * QKV_N + 255) / 256, 256>>>(Wq, Wk, Wv);
    round_kernel<<<(Cc * Cc + 255) / 256, 256>>>(Wo, p_wo, Cc * Cc);
    round_kernel<<<(Cc * FFN_N + 255) / 256, 256>>>(W1, p_w1, Cc * FFN_N);
    round_kernel<<<(FFN_N * Cc + 255) / 256, 256>>>(W2, p_w2, FFN_N * Cc);

    // 1) LN1
    {
        dim3 grid(Cc / 32, Bb), block(32, 8);
        ln_axis1_kernel<<<grid, block>>>(x, gamma1, beta1, p_x1);
    }

    // 2) fused QKV GEMM: [4096,1024] @ [1024,3072]
    {
        dim3 grid(QKV_N / 128, Mrows / 256);
        gemm_mma_kernel<false, false, false, true><<<grid, 256, GEMM_SMEM>>>(
            p_x1, p_wqkv, nullptr, nullptr, p_qkv, Mrows, QKV_N, Cc);
    }

    // 3) causal flash attention
    {
        dim3 grid(Tt / 64, Hh, Bb);
        attn_mma_kernel<<<grid, 128, ATT_SMEM>>>(p_qkv, p_attn);
    }

    // 4) output projection + bias + residual
    {
        dim3 grid(Cc / 128, Mrows / 256);
        gemm_mma_kernel<true, false, true, false><<<grid, 256, GEMM_SMEM>>>(
            p_attn, p_wo, bo, x, p_y, Mrows, Cc, Cc);
    }

    // 5) LN2
    {
        dim3 grid(Cc / 32, Bb), block(32, 8);
        ln_axis1_kernel<<<grid, block>>>(p_y, gamma2, beta2, p_x2);
    }

    // 6) FFN1: h = relu(x2 @ W1 + b1)
    {
        dim3 grid(FFN_N / 128, Mrows / 256);
        gemm_mma_kernel<true, true, false, true><<<grid, 256, GEMM_SMEM>>>(
            p_x2, p_w1, b1, nullptr, p_h, Mrows, FFN_N, Cc);
    }

    // 7) FFN2: out = y + h @ W2 + b2
    {
        dim3 grid(Cc / 128, Mrows / 256);
        gemm_mma_kernel<true, false, true, false><<<grid, 256, GEMM_SMEM>>>(
            p_h, p_w2, b2, p_y, out, Mrows, Cc, FFN_N);
    }
}

// round 7
// speedup vs baseline: 1.5388x; 1.5388x over previous
#include <cuda_runtime.h>
#include <cuda_fp16.h>
#include <math.h>
#include <stdint.h>

// Problem constants
#define Bb   2
#define Tt   2048
#define Cc   1024
#define Hh   16
#define DHd  64
#define Mrows (Bb * Tt)          // 4096
#define QKV_N (3 * Cc)           // 3072
#define FFN_N (4 * Cc)           // 4096
#define ATT_SCALE 0.03125f       // C^-0.5 = 1/32
#define LN_EPS 1e-5f

// ---------------------------------------------------------------------------
// Scratch (static device allocations; no cudaMalloc allowed)
// ---------------------------------------------------------------------------
__device__ __half g_x1  [Mrows * Cc];        // LN1 out (fp16)
__device__ float  g_qkv [Mrows * QKV_N];     // qkv (fp32, tf32-rounded)
__device__ __half g_attn[Mrows * Cc];        // attention out (fp16)
__device__ float  g_y   [Mrows * Cc];        // residual stream (fp32)
__device__ __half g_x2  [Mrows * Cc];        // LN2 out (fp16)
__device__ __half g_h   [Mrows * FFN_N];     // FFN hidden (fp16)
__device__ __half g_wqkv[QKV_N * Cc];        // packed W_qkv^T [3C][C] fp16
__device__ __half g_wo  [Cc * Cc];           // Wo^T  [C][C]  fp16
__device__ __half g_w1  [FFN_N * Cc];        // W1^T  [4C][C] fp16
__device__ __half g_w2  [Cc * FFN_N];        // W2^T  [C][4C] fp16

// ---------------------------------------------------------------------------
// Helpers
// ---------------------------------------------------------------------------
__device__ __forceinline__ float tf32r(float x) {
    uint32_t u;
    asm("cvt.rna.tf32.f32 %0, %1;" : "=r"(u) : "f"(x));
    return __uint_as_float(u);
}
__device__ __forceinline__ void cp_async16(void* smem, const void* gmem) {
    unsigned saddr = (unsigned)__cvta_generic_to_shared(smem);
    asm volatile("cp.async.cg.shared.global [%0], [%1], 16;\n"
                 :: "r"(saddr), "l"(gmem));
}
__device__ __forceinline__ void cp_async_commit() {
    asm volatile("cp.async.commit_group;\n" ::: "memory");
}
__device__ __forceinline__ void cp_async_wait0() {
    asm volatile("cp.async.wait_group 0;\n" ::: "memory");
}
__device__ __forceinline__ void cp_async_wait1() {
    asm volatile("cp.async.wait_group 1;\n" ::: "memory");
}

// tf32 mma (attention)
__device__ __forceinline__ void mma_tf32(float c[4],
                                         const uint32_t a[4],
                                         const uint32_t b[2]) {
    asm volatile(
        "mma.sync.aligned.m16n8k8.row.col.f32.tf32.tf32.f32 "
        "{%0,%1,%2,%3}, {%4,%5,%6,%7}, {%8,%9}, {%0,%1,%2,%3};\n"
        : "+f"(c[0]), "+f"(c[1]), "+f"(c[2]), "+f"(c[3])
        : "r"(a[0]), "r"(a[1]), "r"(a[2]), "r"(a[3]),
          "r"(b[0]), "r"(b[1]));
}

// fp16 mma (GEMMs): m16n8k16, fp32 accum
__device__ __forceinline__ void mma_f16(float c[4],
                                        const uint32_t a[4],
                                        const uint32_t b[2]) {
    asm volatile(
        "mma.sync.aligned.m16n8k16.row.col.f32.f16.f16.f32 "
        "{%0,%1,%2,%3}, {%4,%5,%6,%7}, {%8,%9}, {%0,%1,%2,%3};\n"
        : "+f"(c[0]), "+f"(c[1]), "+f"(c[2]), "+f"(c[3])
        : "r"(a[0]), "r"(a[1]), "r"(a[2]), "r"(a[3]),
          "r"(b[0]), "r"(b[1]));
}

// ---------------------------------------------------------------------------
// Weight prep: transposes to [N][K] fp16
// ---------------------------------------------------------------------------
__global__ __launch_bounds__(256)
void transpose_h_kernel(const float* __restrict__ in,
                        __half* __restrict__ out, int R, int Cn) {
    __shared__ float t[32][33];
    int c0 = blockIdx.x * 32, r0 = blockIdx.y * 32;
    int x = threadIdx.x, y = threadIdx.y;
#pragma unroll
    for (int i = 0; i < 32; i += 8)
        t[y + i][x] = in[(size_t)(r0 + y + i) * Cn + c0 + x];
    __syncthreads();
#pragma unroll
    for (int i = 0; i < 32; i += 8)
        out[(size_t)(c0 + y + i) * R + r0 + x] = __float2half(t[x][y + i]);
}

// pack Wq/Wk/Wv [H,C,DH] -> g_wqkv [3C][C] fp16 (transposed), row n=(sel,h,d)
__global__ __launch_bounds__(256)
void pack_qkv_t_kernel(const float* __restrict__ Wq,
                       const float* __restrict__ Wk,
                       const float* __restrict__ Wv) {
    __shared__ float t[32][33];
    int c0 = blockIdx.x * 32, d0 = blockIdx.y * 32;
    int z = blockIdx.z;
    int sel = z >> 4, h = z & 15;
    const float* W = (sel == 0) ? Wq : (sel == 1) ? Wk : Wv;
    int x = threadIdx.x, y = threadIdx.y;
#pragma unroll
    for (int i = 0; i < 32; i += 8)
        t[y + i][x] = W[(size_t)(h * Cc + c0 + y + i) * DHd + d0 + x];
    __syncthreads();
#pragma unroll
    for (int i = 0; i < 32; i += 8)
        g_wqkv[(size_t)(sel * Cc + h * DHd + d0 + y + i) * Cc + c0 + x] =
            __float2half(t[x][y + i]);
}

// ---------------------------------------------------------------------------
// LayerNorm over axis 1 (TIME), unbiased variance. fp16 output.
// ---------------------------------------------------------------------------
__global__ __launch_bounds__(256)
void ln_axis1_kernel(const float* __restrict__ x,
                     const float* __restrict__ gamma,
                     const float* __restrict__ beta,
                     __half* __restrict__ out) {
    int b  = blockIdx.y;
    int tx = threadIdx.x, ty = threadIdx.y;
    int c  = blockIdx.x * 32 + tx;
    const float* xp = x + (size_t)b * Tt * Cc + c;

    float s = 0.f, s2 = 0.f;
    for (int t = ty; t < Tt; t += 8) {
        float v = xp[(size_t)t * Cc];
        s += v; s2 += v * v;
    }
    __shared__ float ss[8][32], sq[8][32], smean[32], srstd[32];
    ss[ty][tx] = s; sq[ty][tx] = s2;
    __syncthreads();
    if (ty == 0) {
        float S = 0.f, S2 = 0.f;
#pragma unroll
        for (int k = 0; k < 8; k++) { S += ss[k][tx]; S2 += sq[k][tx]; }
        float mean = S / (float)Tt;
        float var  = (S2 - (float)Tt * mean * mean) / (float)(Tt - 1);
        smean[tx] = mean;
        srstd[tx] = rsqrtf(var + LN_EPS);
    }
    __syncthreads();
    float mean = smean[tx], rstd = srstd[tx];
    float g = gamma[c], be = beta[c];
    __half* op = out + (size_t)b * Tt * Cc + c;
    for (int t = ty; t < Tt; t += 8) {
        op[(size_t)t * Cc] = __float2half(g * (xp[(size_t)t * Cc] - mean) * rstd + be);
    }
}

// ---------------------------------------------------------------------------
// FP16 mma.sync GEMM: C[M,N] = epilogue(A[M,K] @ Bt[N,K]^T).
// CTA tile 128x128, BK=32, 256 threads = 8 warps (4m x 2n), warp tile 32x64,
// mma.m16n8k16.f16, fp32 accum. 3-stage cp.async, 2 CTAs/SM.
// A fp16 [M][K]; Bt fp16 [N][K]. M%128==0, N%128==0, K%32==0.
// Smem rows stride 40 halves -> conflict-free fp16x2 fragment loads.
// ---------------------------------------------------------------------------
#define HSTR 40
#define TILE_H (128 * HSTR)                 // halves per tile
#define STG_H  (2 * TILE_H)                 // A + B per stage
#define NSTG 3
#define GEMM_SMEM (NSTG * STG_H * 2)        // bytes = 61440

template<bool BIAS, bool RELU, bool RES, bool ROUND, bool OUTH>
__global__ __launch_bounds__(256, 2)
void gemm_f16_kernel(const __half* __restrict__ A,
                     const __half* __restrict__ Bt,
                     const float* __restrict__ bias,
                     const float* __restrict__ res,
                     void* __restrict__ CoutV,
                     int M, int N, int K) {
    extern __shared__ __half smh[];

    const int tid  = threadIdx.x;
    const int lane = tid & 31;
    const int warp = tid >> 5;
    const int wm   = warp >> 1;
    const int wn   = warp & 1;
    const int gid  = lane >> 2;
    const int tid4 = lane & 3;

    const int row0 = blockIdx.y * 128;
    const int col0 = blockIdx.x * 128;
    const int nIter = K >> 5;

    float acc[2][8][4];
#pragma unroll
    for (int i = 0; i < 2; i++)
#pragma unroll
        for (int j = 0; j < 8; j++)
#pragma unroll
            for (int q = 0; q < 4; q++) acc[i][j][q] = 0.f;

    auto load_stage = [&](int s, int kc) {
        __half* as = smh + s * STG_H;
        __half* bs = as + TILE_H;
        const __half* ap = A  + (size_t)row0 * K + kc * 32;
        const __half* bp = Bt + (size_t)col0 * K + kc * 32;
#pragma unroll
        for (int q = 0; q < 2; q++) {
            int id = tid + 256 * q;
            int r = id >> 2, c8 = (id & 3) << 3;
            cp_async16(&as[r * HSTR + c8], ap + (size_t)r * K + c8);
        }
#pragma unroll
        for (int q = 0; q < 2; q++) {
            int id = tid + 256 * q;
            int r = id >> 2, c8 = (id & 3) << 3;
            cp_async16(&bs[r * HSTR + c8], bp + (size_t)r * K + c8);
        }
        cp_async_commit();
    };

    load_stage(0, 0);
    load_stage(1, 1);

    for (int it = 0; it < nIter; ++it) {
        cp_async_wait1();
        __syncthreads();

        if (it + 2 < nIter) load_stage((it + 2) % NSTG, it + 2);
        else                cp_async_commit();

        const int s = it % NSTG;
        const __half* as = smh + s * STG_H;
        const __half* bs = as + TILE_H;

#pragma unroll
        for (int ks = 0; ks < 2; ks++) {
            const int k0 = ks * 16;
            uint32_t af[2][4];
#pragma unroll
            for (int i = 0; i < 2; i++) {
                int rb = wm * 32 + i * 16 + gid;
                const __half* p0 = &as[rb * HSTR + k0 + 2 * tid4];
                const __half* p1 = &as[(rb + 8) * HSTR + k0 + 2 * tid4];
                af[i][0] = *(const uint32_t*)p0;
                af[i][1] = *(const uint32_t*)p1;
                af[i][2] = *(const uint32_t*)(p0 + 8);
                af[i][3] = *(const uint32_t*)(p1 + 8);
            }
            uint32_t bf[8][2];
#pragma unroll
            for (int j = 0; j < 8; j++) {
                int nb = wn * 64 + j * 8 + gid;
                const __half* p = &bs[nb * HSTR + k0 + 2 * tid4];
                bf[j][0] = *(const uint32_t*)p;
                bf[j][1] = *(const uint32_t*)(p + 8);
            }
#pragma unroll
            for (int i = 0; i < 2; i++)
#pragma unroll
                for (int j = 0; j < 8; j++)
                    mma_f16(acc[i][j], af[i], bf[j]);
        }
    }

    // epilogue
    float*  Cf = (float*)CoutV;
    __half* Ch = (__half*)CoutV;
#pragma unroll
    for (int i = 0; i < 2; i++) {
#pragma unroll
        for (int hr = 0; hr < 2; hr++) {
            int r = row0 + wm * 32 + i * 16 + hr * 8 + gid;
#pragma unroll
            for (int j = 0; j < 8; j++) {
                int cI = col0 + wn * 64 + j * 8 + 2 * tid4;
                float v0 = acc[i][j][hr * 2];
                float v1 = acc[i][j][hr * 2 + 1];
                if (BIAS) {
                    float2 bi = *(const float2*)&bias[cI];
                    v0 += bi.x; v1 += bi.y;
                }
                if (RES) {
                    float2 rv = *(const float2*)&res[(size_t)r * N + cI];
                    v0 += rv.x; v1 += rv.y;
                }
                if (RELU) { v0 = fmaxf(v0, 0.f); v1 = fmaxf(v1, 0.f); }
                if (OUTH) {
                    *(__half2*)&Ch[(size_t)r * N + cI] = __floats2half2_rn(v0, v1);
                } else {
                    if (ROUND) { v0 = tf32r(v0); v1 = tf32r(v1); }
                    *(float2*)&Cf[(size_t)r * N + cI] = make_float2(v0, v1);
                }
            }
        }
    }
}

// ---------------------------------------------------------------------------
// Causal flash attention, tf32 mma.sync (Round-3 PASS), fp16 output.
// ---------------------------------------------------------------------------
#define KSTR 68
#define VSTR 72
#define ATT_SMEM ((64*KSTR + 2*64*KSTR + 2*64*VSTR) * 4)

__global__ __launch_bounds__(128, 2)
void attn_mma_kernel(const float* __restrict__ qkv, __half* __restrict__ outp) {
    extern __shared__ float sh[];
    float* Qs = sh;
    float* Ks = Qs + 64 * KSTR;
    float* Vs = Ks + 2 * 64 * KSTR;

    const int qt = blockIdx.x, h = blockIdx.y, b = blockIdx.z;
    const int t0 = qt * 64;
    const int tid  = threadIdx.x;
    const int lane = tid & 31;
    const int warp = tid >> 5;
    const int gid  = lane >> 2;
    const int tid4 = lane & 3;
    const unsigned FULL = 0xffffffffu;

    const float* base = qkv + (size_t)(b * Tt) * QKV_N + h * 64;

#pragma unroll
    for (int r = 0; r < 8; r++) {
        int id  = tid + 128 * r;
        int row = id >> 4;
        int qc  = (id & 15) * 4;
        float4 v = *(const float4*)(base + (size_t)(t0 + row) * QKV_N + qc);
        Qs[row * KSTR + qc + 0] = v.x * ATT_SCALE;
        Qs[row * KSTR + qc + 1] = v.y * ATT_SCALE;
        Qs[row * KSTR + qc + 2] = v.z * ATT_SCALE;
        Qs[row * KSTR + qc + 3] = v.w * ATT_SCALE;
    }

    {
        const float* kb = base + Cc;
        const float* vb = base + 2 * Cc;
#pragma unroll
        for (int r = 0; r < 8; r++) {
            int id  = tid + 128 * r;
            int row = id >> 4;
            int qc  = (id & 15) * 4;
            cp_async16(&Ks[row * KSTR + qc], kb + (size_t)row * QKV_N + qc);
            cp_async16(&Vs[row * VSTR + qc], vb + (size_t)row * QKV_N + qc);
        }
        cp_async_commit();
    }
    __syncthreads();

    uint32_t qa[8][4];
    {
        int rb = (16 * warp + gid) * KSTR;
#pragma unroll
        for (int k = 0; k < 8; k++) {
            qa[k][0] = __float_as_uint(Qs[rb + 8 * k + tid4]);
            qa[k][1] = __float_as_uint(Qs[rb + 8 * KSTR + 8 * k + tid4]);
            qa[k][2] = __float_as_uint(Qs[rb + 8 * k + tid4 + 4]);
            qa[k][3] = __float_as_uint(Qs[rb + 8 * KSTR + 8 * k + tid4 + 4]);
        }
    }

    float m0 = -1e30f, m1 = -1e30f, l0 = 0.f, l1 = 0.f;
    float o[8][4];
#pragma unroll
    for (int j = 0; j < 8; j++)
#pragma unroll
        for (int q = 0; q < 4; q++) o[j][q] = 0.f;

    const int nt = qt + 1;
    for (int it = 0; it < nt; ++it) {
        const int buf = it & 1;
        float* Kb = Ks + buf * 64 * KSTR;
        float* Vb = Vs + buf * 64 * VSTR;

        cp_async_wait0();
        __syncthreads();

        if (it + 1 < nt) {
            const int s0 = (it + 1) * 64;
            float* Kn = Ks + (buf ^ 1) * 64 * KSTR;
            float* Vn = Vs + (buf ^ 1) * 64 * VSTR;
            const float* kb = base + Cc     + (size_t)s0 * QKV_N;
            const float* vb = base + 2 * Cc + (size_t)s0 * QKV_N;
#pragma unroll
            for (int r = 0; r < 8; r++) {
                int id  = tid + 128 * r;
                int row = id >> 4;
                int qc  = (id & 15) * 4;
                cp_async16(&Kn[row * KSTR + qc], kb + (size_t)row * QKV_N + qc);
                cp_async16(&Vn[row * VSTR + qc], vb + (size_t)row * QKV_N + qc);
            }
            cp_async_commit();
        }

        float sc[8][4];
#pragma unroll
        for (int j = 0; j < 8; j++)
#pragma unroll
            for (int q = 0; q < 4; q++) sc[j][q] = 0.f;
#pragma unroll
        for (int k = 0; k < 8; k++) {
            uint32_t kb2[8][2];
#pragma unroll
            for (int j = 0; j < 8; j++) {
                int rb = (8 * j + gid) * KSTR + 8 * k;
                kb2[j][0] = __float_as_uint(Kb[rb + tid4]);
                kb2[j][1] = __float_as_uint(Kb[rb + tid4 + 4]);
            }
#pragma unroll
            for (int j = 0; j < 8; j++)
                mma_tf32(sc[j], qa[k], kb2[j]);
        }

        if (it == qt) {
            int r0 = 16 * warp + gid;
#pragma unroll
            for (int j = 0; j < 8; j++) {
                int c0 = 8 * j + 2 * tid4;
                if (c0     > r0)     sc[j][0] = -1e30f;
                if (c0 + 1 > r0)     sc[j][1] = -1e30f;
                if (c0     > r0 + 8) sc[j][2] = -1e30f;
                if (c0 + 1 > r0 + 8) sc[j][3] = -1e30f;
            }
        }

        float mx0 = -1e30f, mx1 = -1e30f;
#pragma unroll
        for (int j = 0; j < 8; j++) {
            mx0 = fmaxf(mx0, fmaxf(sc[j][0], sc[j][1]));
            mx1 = fmaxf(mx1, fmaxf(sc[j][2], sc[j][3]));
        }
        mx0 = fmaxf(mx0, __shfl_xor_sync(FULL, mx0, 1));
        mx0 = fmaxf(mx0, __shfl_xor_sync(FULL, mx0, 2));
        mx1 = fmaxf(mx1, __shfl_xor_sync(FULL, mx1, 1));
        mx1 = fmaxf(mx1, __shfl_xor_sync(FULL, mx1, 2));
        float mn0 = fmaxf(m0, mx0), mn1 = fmaxf(m1, mx1);
        float sum0 = 0.f, sum1 = 0.f;
#pragma unroll
        for (int j = 0; j < 8; j++) {
            sc[j][0] = __expf(sc[j][0] - mn0);
            sc[j][1] = __expf(sc[j][1] - mn0);
            sc[j][2] = __expf(sc[j][2] - mn1);
            sc[j][3] = __expf(sc[j][3] - mn1);
            sum0 += sc[j][0] + sc[j][1];
            sum1 += sc[j][2] + sc[j][3];
        }
        sum0 += __shfl_xor_sync(FULL, sum0, 1);
        sum0 += __shfl_xor_sync(FULL, sum0, 2);
        sum1 += __shfl_xor_sync(FULL, sum1, 1);
        sum1 += __shfl_xor_sync(FULL, sum1, 2);
        float c0 = __expf(m0 - mn0), c1 = __expf(m1 - mn1);
        l0 = l0 * c0 + sum0;
        l1 = l1 * c1 + sum1;
        m0 = mn0; m1 = mn1;
#pragma unroll
        for (int j = 0; j < 8; j++) {
            o[j][0] *= c0; o[j][1] *= c0;
            o[j][2] *= c1; o[j][3] *= c1;
        }

        __syncthreads();
        {
            int pr0 = (16 * warp + gid) * KSTR;
            int pr1 = pr0 + 8 * KSTR;
#pragma unroll
            for (int j = 0; j < 8; j++) {
                int cI = 8 * j + 2 * tid4;
                Kb[pr0 + cI]     = tf32r(sc[j][0]);
                Kb[pr0 + cI + 1] = tf32r(sc[j][1]);
                Kb[pr1 + cI]     = tf32r(sc[j][2]);
                Kb[pr1 + cI + 1] = tf32r(sc[j][3]);
            }
        }
        __syncwarp();

#pragma unroll
        for (int k = 0; k < 8; k++) {
            uint32_t pa[4];
            int pb = (16 * warp + gid) * KSTR + 8 * k;
            pa[0] = __float_as_uint(Kb[pb + tid4]);
            pa[1] = __float_as_uint(Kb[pb + 8 * KSTR + tid4]);
            pa[2] = __float_as_uint(Kb[pb + tid4 + 4]);
            pa[3] = __float_as_uint(Kb[pb + 8 * KSTR + tid4 + 4]);
            uint32_t vb2[8][2];
#pragma unroll
            for (int j = 0; j < 8; j++) {
                vb2[j][0] = __float_as_uint(Vb[(8 * k + tid4) * VSTR + 8 * j + gid]);
                vb2[j][1] = __float_as_uint(Vb[(8 * k + tid4 + 4) * VSTR + 8 * j + gid]);
            }
#pragma unroll
            for (int j = 0; j < 8; j++)
                mma_tf32(o[j], pa, vb2[j]);
        }
    }

    float inv0 = 1.f / l0, inv1 = 1.f / l1;
    int r0 = t0 + 16 * warp + gid;
#pragma unroll
    for (int j = 0; j < 8; j++) {
        int cI = h * 64 + 8 * j + 2 * tid4;
        __half2 v0 = __floats2half2_rn(o[j][0] * inv0, o[j][1] * inv0);
        __half2 v1 = __floats2half2_rn(o[j][2] * inv1, o[j][3] * inv1);
        *(__half2*)&outp[(size_t)(b * Tt + r0) * Cc + cI]     = v0;
        *(__half2*)&outp[(size_t)(b * Tt + r0 + 8) * Cc + cI] = v1;
    }
}

// ---------------------------------------------------------------------------
// Launch
// ---------------------------------------------------------------------------
extern "C" void kernel_launch(void* const* d_in, const int* in_sizes, int n_in,
                              void* d_out, int out_size) {
    const float* x      = (const float*)d_in[0];
    const float* Wq     = (const float*)d_in[1];
    const float* Wk     = (const float*)d_in[2];
    const float* Wv     = (const float*)d_in[3];
    const float* Wo     = (const float*)d_in[4];
    const float* bo     = (const float*)d_in[5];
    const float* W1     = (const float*)d_in[6];
    const float* b1     = (const float*)d_in[7];
    const float* W2     = (const float*)d_in[8];
    const float* b2     = (const float*)d_in[9];
    const float* gamma1 = (const float*)d_in[10];
    const float* beta1  = (const float*)d_in[11];
    const float* gamma2 = (const float*)d_in[12];
    const float* beta2  = (const float*)d_in[13];
    float* out = (float*)d_out;

    __half *p_x1, *p_attn, *p_x2, *p_h, *p_wqkv, *p_wo, *p_w1, *p_w2;
    float *p_qkv, *p_y;
    cudaGetSymbolAddress((void**)&p_x1,   g_x1);
    cudaGetSymbolAddress((void**)&p_qkv,  g_qkv);
    cudaGetSymbolAddress((void**)&p_attn, g_attn);
    cudaGetSymbolAddress((void**)&p_y,    g_y);
    cudaGetSymbolAddress((void**)&p_x2,   g_x2);
    cudaGetSymbolAddress((void**)&p_h,    g_h);
    cudaGetSymbolAddress((void**)&p_wqkv, g_wqkv);
    cudaGetSymbolAddress((void**)&p_wo,   g_wo);
    cudaGetSymbolAddress((void**)&p_w1,   g_w1);
    cudaGetSymbolAddress((void**)&p_w2,   g_w2);

    cudaFuncSetAttribute(gemm_f16_kernel<false, false, false, true, false>,
                         cudaFuncAttributeMaxDynamicSharedMemorySize, GEMM_SMEM);
    cudaFuncSetAttribute(gemm_f16_kernel<true, false, true, false, false>,
                         cudaFuncAttributeMaxDynamicSharedMemorySize, GEMM_SMEM);
    cudaFuncSetAttribute(gemm_f16_kernel<true, true, false, false, true>,
                         cudaFuncAttributeMaxDynamicSharedMemorySize, GEMM_SMEM);
    cudaFuncSetAttribute(attn_mma_kernel,
                         cudaFuncAttributeMaxDynamicSharedMemorySize, ATT_SMEM);

    dim3 tb(32, 8);

    // 0) weight prep: transpose to [N][K] fp16
    pack_qkv_t_kernel<<<dim3(Cc / 32, DHd / 32, 48), tb>>>(Wq, Wk, Wv);
    transpose_h_kernel<<<dim3(Cc / 32, Cc / 32), tb>>>(Wo, p_wo, Cc, Cc);
    transpose_h_kernel<<<dim3(FFN_N / 32, Cc / 32), tb>>>(W1, p_w1, Cc, FFN_N);
    transpose_h_kernel<<<dim3(Cc / 32, FFN_N / 32), tb>>>(W2, p_w2, FFN_N, Cc);

    // 1) LN1 -> fp16
    {
        dim3 grid(Cc / 32, Bb), block(32, 8);
        ln_axis1_kernel<<<grid, block>>>(x, gamma1, beta1, p_x1);
    }

    // 2) fused QKV GEMM (fp16 mma): out fp32 tf32-rounded for attention
    {
        dim3 grid(QKV_N / 128, Mrows / 128);
        gemm_f16_kernel<false, false, false, true, false><<<grid, 256, GEMM_SMEM>>>(
            p_x1, p_wqkv, nullptr, nullptr, p_qkv, Mrows, QKV_N, Cc);
    }

    // 3) causal flash attention (tf32) -> fp16 out
    {
        dim3 grid(Tt / 64, Hh, Bb);
        attn_mma_kernel<<<grid, 128, ATT_SMEM>>>(p_qkv, p_attn);
    }

    // 4) output projection + bias + residual -> y fp32
    {
        dim3 grid(Cc / 128, Mrows / 128);
        gemm_f16_kernel<true, false, true, false, false><<<grid, 256, GEMM_SMEM>>>(
            p_attn, p_wo, bo, x, p_y, Mrows, Cc, Cc);
    }

    // 5) LN2 -> fp16
    {
        dim3 grid(Cc / 32, Bb), block(32, 8);
        ln_axis1_kernel<<<grid, block>>>(p_y, gamma2, beta2, p_x2);
    }

    // 6) FFN1: h = relu(x2 @ W1 + b1) -> fp16
    {
        dim3 grid(FFN_N / 128, Mrows / 128);
        gemm_f16_kernel<true, true, false, false, true><<<grid, 256, GEMM_SMEM>>>(
            p_x2, p_w1, b1, nullptr, p_h, Mrows, FFN_N, Cc);
    }

    // 7) FFN2: out = y + h @ W2 + b2 -> fp32
    {
        dim3 grid(Cc / 128, Mrows / 128);
        gemm_f16_kernel<true, false, true, false, false><<<grid, 256, GEMM_SMEM>>>(
            p_h, p_w2, b2, p_y, out, Mrows, Cc, FFN_N);
    }
}

// round 8
// speedup vs baseline: 1.7492x; 1.1367x over previous
#include <cuda_runtime.h>
#include <cuda_fp16.h>
#include <math.h>
#include <stdint.h>

// Problem constants
#define Bb   2
#define Tt   2048
#define Cc   1024
#define Hh   16
#define DHd  64
#define Mrows (Bb * Tt)          // 4096
#define QKV_N (3 * Cc)           // 3072
#define FFN_N (4 * Cc)           // 4096
#define ATT_SCALE 0.03125f       // C^-0.5 = 1/32
#define LN_EPS 1e-5f

// ---------------------------------------------------------------------------
// Scratch (static device allocations; no cudaMalloc allowed)
// ---------------------------------------------------------------------------
__device__ __half g_x1  [Mrows * Cc];        // LN1 out (fp16)
__device__ __half g_qkv [Mrows * QKV_N];     // qkv (fp16; Q pre-scaled)
__device__ __half g_vT  [Bb * Hh * DHd * Tt];// V transposed [b][h][d][T] fp16
__device__ __half g_attn[Mrows * Cc];        // attention out (fp16)
__device__ float  g_y   [Mrows * Cc];        // residual stream (fp32)
__device__ __half g_x2  [Mrows * Cc];        // LN2 out (fp16)
__device__ __half g_h   [Mrows * FFN_N];     // FFN hidden (fp16)
__device__ __half g_wqkv[QKV_N * Cc];        // packed W_qkv^T [3C][C] fp16
__device__ __half g_wo  [Cc * Cc];           // Wo^T  [C][C]  fp16
__device__ __half g_w1  [FFN_N * Cc];        // W1^T  [4C][C] fp16
__device__ __half g_w2  [Cc * FFN_N];        // W2^T  [C][4C] fp16

// ---------------------------------------------------------------------------
// Helpers
// ---------------------------------------------------------------------------
__device__ __forceinline__ float tf32r(float x) {
    uint32_t u;
    asm("cvt.rna.tf32.f32 %0, %1;" : "=r"(u) : "f"(x));
    return __uint_as_float(u);
}
__device__ __forceinline__ void cp_async16(void* smem, const void* gmem) {
    unsigned saddr = (unsigned)__cvta_generic_to_shared(smem);
    asm volatile("cp.async.cg.shared.global [%0], [%1], 16;\n"
                 :: "r"(saddr), "l"(gmem));
}
__device__ __forceinline__ void cp_async_commit() {
    asm volatile("cp.async.commit_group;\n" ::: "memory");
}
__device__ __forceinline__ void cp_async_wait0() {
    asm volatile("cp.async.wait_group 0;\n" ::: "memory");
}
__device__ __forceinline__ void cp_async_wait1() {
    asm volatile("cp.async.wait_group 1;\n" ::: "memory");
}

// fp16 mma: m16n8k16, fp32 accum
__device__ __forceinline__ void mma_f16(float c[4],
                                        const uint32_t a[4],
                                        const uint32_t b[2]) {
    asm volatile(
        "mma.sync.aligned.m16n8k16.row.col.f32.f16.f16.f32 "
        "{%0,%1,%2,%3}, {%4,%5,%6,%7}, {%8,%9}, {%0,%1,%2,%3};\n"
        : "+f"(c[0]), "+f"(c[1]), "+f"(c[2]), "+f"(c[3])
        : "r"(a[0]), "r"(a[1]), "r"(a[2]), "r"(a[3]),
          "r"(b[0]), "r"(b[1]));
}
__device__ __forceinline__ uint32_t pack_h2(float a, float b) {
    __half2 h = __floats2half2_rn(a, b);
    return *(uint32_t*)&h;
}

// ---------------------------------------------------------------------------
// Weight prep
// ---------------------------------------------------------------------------
__global__ __launch_bounds__(256)
void transpose_h_kernel(const float* __restrict__ in,
                        __half* __restrict__ out, int R, int Cn) {
    __shared__ float t[32][33];
    int c0 = blockIdx.x * 32, r0 = blockIdx.y * 32;
    int x = threadIdx.x, y = threadIdx.y;
#pragma unroll
    for (int i = 0; i < 32; i += 8)
        t[y + i][x] = in[(size_t)(r0 + y + i) * Cn + c0 + x];
    __syncthreads();
#pragma unroll
    for (int i = 0; i < 32; i += 8)
        out[(size_t)(c0 + y + i) * R + r0 + x] = __float2half(t[x][y + i]);
}

// pack Wq/Wk/Wv [H,C,DH] -> g_wqkv [3C][C] fp16 (transposed).
// ATT_SCALE is folded into Wq so Q comes out pre-scaled.
__global__ __launch_bounds__(256)
void pack_qkv_t_kernel(const float* __restrict__ Wq,
                       const float* __restrict__ Wk,
                       const float* __restrict__ Wv) {
    __shared__ float t[32][33];
    int c0 = blockIdx.x * 32, d0 = blockIdx.y * 32;
    int z = blockIdx.z;
    int sel = z >> 4, h = z & 15;
    const float* W = (sel == 0) ? Wq : (sel == 1) ? Wk : Wv;
    float scl = (sel == 0) ? ATT_SCALE : 1.0f;
    int x = threadIdx.x, y = threadIdx.y;
#pragma unroll
    for (int i = 0; i < 32; i += 8)
        t[y + i][x] = W[(size_t)(h * Cc + c0 + y + i) * DHd + d0 + x];
    __syncthreads();
#pragma unroll
    for (int i = 0; i < 32; i += 8)
        g_wqkv[(size_t)(sel * Cc + h * DHd + d0 + y + i) * Cc + c0 + x] =
            __float2half(t[x][y + i] * scl);
}

// V slice of qkv [t][2048 + h*64 + d] -> g_vT [(b*Hh+h)*64 + d][t]
__global__ __launch_bounds__(256)
void transpose_v_kernel(const __half* __restrict__ qkv,
                        __half* __restrict__ vT) {
    __shared__ __half t[32][33];
    int t0 = blockIdx.x * 32, d0 = blockIdx.y * 32;
    int z = blockIdx.z;
    int b = z >> 4, h = z & 15;
    int x = threadIdx.x, y = threadIdx.y;
#pragma unroll
    for (int i = 0; i < 32; i += 8)
        t[y + i][x] = qkv[(size_t)(b * Tt + t0 + y + i) * QKV_N
                          + 2 * Cc + h * DHd + d0 + x];
    __syncthreads();
#pragma unroll
    for (int i = 0; i < 32; i += 8)
        vT[(size_t)((b * Hh + h) * DHd + d0 + y + i) * Tt + t0 + x] = t[x][y + i];
}

// ---------------------------------------------------------------------------
// LayerNorm over axis 1 (TIME), unbiased variance. fp16 output.
// ---------------------------------------------------------------------------
__global__ __launch_bounds__(256)
void ln_axis1_kernel(const float* __restrict__ x,
                     const float* __restrict__ gamma,
                     const float* __restrict__ beta,
                     __half* __restrict__ out) {
    int b  = blockIdx.y;
    int tx = threadIdx.x, ty = threadIdx.y;
    int c  = blockIdx.x * 32 + tx;
    const float* xp = x + (size_t)b * Tt * Cc + c;

    float s = 0.f, s2 = 0.f;
    for (int t = ty; t < Tt; t += 8) {
        float v = xp[(size_t)t * Cc];
        s += v; s2 += v * v;
    }
    __shared__ float ss[8][32], sq[8][32], smean[32], srstd[32];
    ss[ty][tx] = s; sq[ty][tx] = s2;
    __syncthreads();
    if (ty == 0) {
        float S = 0.f, S2 = 0.f;
#pragma unroll
        for (int k = 0; k < 8; k++) { S += ss[k][tx]; S2 += sq[k][tx]; }
        float mean = S / (float)Tt;
        float var  = (S2 - (float)Tt * mean * mean) / (float)(Tt - 1);
        smean[tx] = mean;
        srstd[tx] = rsqrtf(var + LN_EPS);
    }
    __syncthreads();
    float mean = smean[tx], rstd = srstd[tx];
    float g = gamma[c], be = beta[c];
    __half* op = out + (size_t)b * Tt * Cc + c;
    for (int t = ty; t < Tt; t += 8) {
        op[(size_t)t * Cc] = __float2half(g * (xp[(size_t)t * Cc] - mean) * rstd + be);
    }
}

// ---------------------------------------------------------------------------
// FP16 mma.sync GEMM (unchanged from Round 7 PASS).
// ---------------------------------------------------------------------------
#define HSTR 40
#define TILE_H (128 * HSTR)
#define STG_H  (2 * TILE_H)
#define NSTG 3
#define GEMM_SMEM (NSTG * STG_H * 2)

template<bool BIAS, bool RELU, bool RES, bool ROUND, bool OUTH>
__global__ __launch_bounds__(256, 2)
void gemm_f16_kernel(const __half* __restrict__ A,
                     const __half* __restrict__ Bt,
                     const float* __restrict__ bias,
                     const float* __restrict__ res,
                     void* __restrict__ CoutV,
                     int M, int N, int K) {
    extern __shared__ __half smh[];

    const int tid  = threadIdx.x;
    const int lane = tid & 31;
    const int warp = tid >> 5;
    const int wm   = warp >> 1;
    const int wn   = warp & 1;
    const int gid  = lane >> 2;
    const int tid4 = lane & 3;

    const int row0 = blockIdx.y * 128;
    const int col0 = blockIdx.x * 128;
    const int nIter = K >> 5;

    float acc[2][8][4];
#pragma unroll
    for (int i = 0; i < 2; i++)
#pragma unroll
        for (int j = 0; j < 8; j++)
#pragma unroll
            for (int q = 0; q < 4; q++) acc[i][j][q] = 0.f;

    auto load_stage = [&](int s, int kc) {
        __half* as = smh + s * STG_H;
        __half* bs = as + TILE_H;
        const __half* ap = A  + (size_t)row0 * K + kc * 32;
        const __half* bp = Bt + (size_t)col0 * K + kc * 32;
#pragma unroll
        for (int q = 0; q < 2; q++) {
            int id = tid + 256 * q;
            int r = id >> 2, c8 = (id & 3) << 3;
            cp_async16(&as[r * HSTR + c8], ap + (size_t)r * K + c8);
        }
#pragma unroll
        for (int q = 0; q < 2; q++) {
            int id = tid + 256 * q;
            int r = id >> 2, c8 = (id & 3) << 3;
            cp_async16(&bs[r * HSTR + c8], bp + (size_t)r * K + c8);
        }
        cp_async_commit();
    };

    load_stage(0, 0);
    load_stage(1, 1);

    for (int it = 0; it < nIter; ++it) {
        cp_async_wait1();
        __syncthreads();

        if (it + 2 < nIter) load_stage((it + 2) % NSTG, it + 2);
        else                cp_async_commit();

        const int s = it % NSTG;
        const __half* as = smh + s * STG_H;
        const __half* bs = as + TILE_H;

#pragma unroll
        for (int ks = 0; ks < 2; ks++) {
            const int k0 = ks * 16;
            uint32_t af[2][4];
#pragma unroll
            for (int i = 0; i < 2; i++) {
                int rb = wm * 32 + i * 16 + gid;
                const __half* p0 = &as[rb * HSTR + k0 + 2 * tid4];
                const __half* p1 = &as[(rb + 8) * HSTR + k0 + 2 * tid4];
                af[i][0] = *(const uint32_t*)p0;
                af[i][1] = *(const uint32_t*)p1;
                af[i][2] = *(const uint32_t*)(p0 + 8);
                af[i][3] = *(const uint32_t*)(p1 + 8);
            }
            uint32_t bf[8][2];
#pragma unroll
            for (int j = 0; j < 8; j++) {
                int nb = wn * 64 + j * 8 + gid;
                const __half* p = &bs[nb * HSTR + k0 + 2 * tid4];
                bf[j][0] = *(const uint32_t*)p;
                bf[j][1] = *(const uint32_t*)(p + 8);
            }
#pragma unroll
            for (int i = 0; i < 2; i++)
#pragma unroll
                for (int j = 0; j < 8; j++)
                    mma_f16(acc[i][j], af[i], bf[j]);
        }
    }

    float*  Cf = (float*)CoutV;
    __half* Ch = (__half*)CoutV;
#pragma unroll
    for (int i = 0; i < 2; i++) {
#pragma unroll
        for (int hr = 0; hr < 2; hr++) {
            int r = row0 + wm * 32 + i * 16 + hr * 8 + gid;
#pragma unroll
            for (int j = 0; j < 8; j++) {
                int cI = col0 + wn * 64 + j * 8 + 2 * tid4;
                float v0 = acc[i][j][hr * 2];
                float v1 = acc[i][j][hr * 2 + 1];
                if (BIAS) {
                    float2 bi = *(const float2*)&bias[cI];
                    v0 += bi.x; v1 += bi.y;
                }
                if (RES) {
                    float2 rv = *(const float2*)&res[(size_t)r * N + cI];
                    v0 += rv.x; v1 += rv.y;
                }
                if (RELU) { v0 = fmaxf(v0, 0.f); v1 = fmaxf(v1, 0.f); }
                if (OUTH) {
                    *(__half2*)&Ch[(size_t)r * N + cI] = __floats2half2_rn(v0, v1);
                } else {
                    if (ROUND) { v0 = tf32r(v0); v1 = tf32r(v1); }
                    *(float2*)&Cf[(size_t)r * N + cI] = make_float2(v0, v1);
                }
            }
        }
    }
}

// ---------------------------------------------------------------------------
// Causal flash attention, fp16 mma (m16n8k16), register-direct P.
// BQ=BS=64, DH=64, 128 threads = 4 warps; warp w owns Q rows 16w..16w+15.
// Q pre-scaled (ATT_SCALE in Wq). K from qkv fp16; V from g_vT [d][T].
// Smem stride 72 halves -> conflict-free fragment loads.
// ---------------------------------------------------------------------------
#define AST 72
#define ATT_SMEM ((64 + 128 + 128) * AST * 2)    // 46080 bytes

__global__ __launch_bounds__(128, 2)
void attn_f16_kernel(const __half* __restrict__ qkv,
                     const __half* __restrict__ vT,
                     __half* __restrict__ outp) {
    extern __shared__ __half sha[];
    __half* Qs = sha;                   // [64][AST]
    __half* Ks = Qs + 64 * AST;         // [2][64][AST]
    __half* Vs = Ks + 2 * 64 * AST;     // [2][64][AST]  (rows = d, cols = s)

    const int qt = blockIdx.x, h = blockIdx.y, b = blockIdx.z;
    const int t0 = qt * 64;
    const int tid  = threadIdx.x;
    const int lane = tid & 31;
    const int warp = tid >> 5;
    const int gid  = lane >> 2;
    const int tid4 = lane & 3;
    const unsigned FULL = 0xffffffffu;

    const __half* qb = qkv + (size_t)(b * Tt) * QKV_N + h * DHd;
    const __half* kb = qkv + (size_t)(b * Tt) * QKV_N + Cc + h * DHd;
    const __half* vb = vT + (size_t)((b * Hh + h) * DHd) * Tt;

    // prefetch Q tile + K0/V0 (one group)
#pragma unroll
    for (int q = 0; q < 4; q++) {
        int id  = tid + 128 * q;
        int row = id >> 3;
        int c8  = (id & 7) * 8;
        cp_async16(&Qs[row * AST + c8], qb + (size_t)(t0 + row) * QKV_N + c8);
        cp_async16(&Ks[row * AST + c8], kb + (size_t)row * QKV_N + c8);
        cp_async16(&Vs[row * AST + c8], vb + (size_t)row * Tt + c8);
    }
    cp_async_commit();
    cp_async_wait0();
    __syncthreads();

    // Q fragments register-resident (4 k-steps of m16n8k16)
    uint32_t qa[4][4];
    {
        int rb = 16 * warp + gid;
#pragma unroll
        for (int k = 0; k < 4; k++) {
            const __half* p0 = &Qs[rb * AST + 16 * k + 2 * tid4];
            const __half* p1 = &Qs[(rb + 8) * AST + 16 * k + 2 * tid4];
            qa[k][0] = *(const uint32_t*)p0;
            qa[k][1] = *(const uint32_t*)p1;
            qa[k][2] = *(const uint32_t*)(p0 + 8);
            qa[k][3] = *(const uint32_t*)(p1 + 8);
        }
    }

    float m0 = -1e30f, m1 = -1e30f, l0 = 0.f, l1 = 0.f;
    float o[8][4];
#pragma unroll
    for (int j = 0; j < 8; j++)
#pragma unroll
        for (int q = 0; q < 4; q++) o[j][q] = 0.f;

    const int nt = qt + 1;
    for (int it = 0; it < nt; ++it) {
        const int buf = it & 1;
        __half* Kb = Ks + buf * 64 * AST;
        __half* Vb = Vs + buf * 64 * AST;

        cp_async_wait0();
        __syncthreads();

        if (it + 1 < nt) {
            const int s0 = (it + 1) * 64;
            __half* Kn = Ks + (buf ^ 1) * 64 * AST;
            __half* Vn = Vs + (buf ^ 1) * 64 * AST;
#pragma unroll
            for (int q = 0; q < 4; q++) {
                int id  = tid + 128 * q;
                int row = id >> 3;
                int c8  = (id & 7) * 8;
                cp_async16(&Kn[row * AST + c8],
                           kb + (size_t)(s0 + row) * QKV_N + c8);
                cp_async16(&Vn[row * AST + c8],
                           vb + (size_t)row * Tt + s0 + c8);
            }
            cp_async_commit();
        }

        // ---- S = Q K^T (4 fp16 k-steps) ----
        float sc[8][4];
#pragma unroll
        for (int j = 0; j < 8; j++)
#pragma unroll
            for (int q = 0; q < 4; q++) sc[j][q] = 0.f;
#pragma unroll
        for (int ks = 0; ks < 4; ks++) {
            uint32_t kf[8][2];
#pragma unroll
            for (int j = 0; j < 8; j++) {
                const __half* p = &Kb[(8 * j + gid) * AST + 16 * ks + 2 * tid4];
                kf[j][0] = *(const uint32_t*)p;
                kf[j][1] = *(const uint32_t*)(p + 8);
            }
#pragma unroll
            for (int j = 0; j < 8; j++)
                mma_f16(sc[j], qa[ks], kf[j]);
        }

        // ---- causal mask on diagonal tile ----
        if (it == qt) {
            int r0 = 16 * warp + gid;
#pragma unroll
            for (int j = 0; j < 8; j++) {
                int c0 = 8 * j + 2 * tid4;
                if (c0     > r0)     sc[j][0] = -1e30f;
                if (c0 + 1 > r0)     sc[j][1] = -1e30f;
                if (c0     > r0 + 8) sc[j][2] = -1e30f;
                if (c0 + 1 > r0 + 8) sc[j][3] = -1e30f;
            }
        }

        // ---- online softmax ----
        float mx0 = -1e30f, mx1 = -1e30f;
#pragma unroll
        for (int j = 0; j < 8; j++) {
            mx0 = fmaxf(mx0, fmaxf(sc[j][0], sc[j][1]));
            mx1 = fmaxf(mx1, fmaxf(sc[j][2], sc[j][3]));
        }
        mx0 = fmaxf(mx0, __shfl_xor_sync(FULL, mx0, 1));
        mx0 = fmaxf(mx0, __shfl_xor_sync(FULL, mx0, 2));
        mx1 = fmaxf(mx1, __shfl_xor_sync(FULL, mx1, 1));
        mx1 = fmaxf(mx1, __shfl_xor_sync(FULL, mx1, 2));
        float mn0 = fmaxf(m0, mx0), mn1 = fmaxf(m1, mx1);
        float sum0 = 0.f, sum1 = 0.f;
#pragma unroll
        for (int j = 0; j < 8; j++) {
            sc[j][0] = __expf(sc[j][0] - mn0);
            sc[j][1] = __expf(sc[j][1] - mn0);
            sc[j][2] = __expf(sc[j][2] - mn1);
            sc[j][3] = __expf(sc[j][3] - mn1);
            sum0 += sc[j][0] + sc[j][1];
            sum1 += sc[j][2] + sc[j][3];
        }
        sum0 += __shfl_xor_sync(FULL, sum0, 1);
        sum0 += __shfl_xor_sync(FULL, sum0, 2);
        sum1 += __shfl_xor_sync(FULL, sum1, 1);
        sum1 += __shfl_xor_sync(FULL, sum1, 2);
        float c0 = __expf(m0 - mn0), c1 = __expf(m1 - mn1);
        l0 = l0 * c0 + sum0;
        l1 = l1 * c1 + sum1;
        m0 = mn0; m1 = mn1;
#pragma unroll
        for (int j = 0; j < 8; j++) {
            o[j][0] *= c0; o[j][1] *= c0;
            o[j][2] *= c1; o[j][3] *= c1;
        }

        // ---- O += P V : P packs directly from sc registers (A-frag layout) ----
#pragma unroll
        for (int ks = 0; ks < 4; ks++) {
            uint32_t pa[4];
            pa[0] = pack_h2(sc[2 * ks][0],     sc[2 * ks][1]);
            pa[1] = pack_h2(sc[2 * ks][2],     sc[2 * ks][3]);
            pa[2] = pack_h2(sc[2 * ks + 1][0], sc[2 * ks + 1][1]);
            pa[3] = pack_h2(sc[2 * ks + 1][2], sc[2 * ks + 1][3]);
            uint32_t vf[8][2];
#pragma unroll
            for (int j = 0; j < 8; j++) {
                const __half* p = &Vb[(8 * j + gid) * AST + 16 * ks + 2 * tid4];
                vf[j][0] = *(const uint32_t*)p;
                vf[j][1] = *(const uint32_t*)(p + 8);
            }
#pragma unroll
            for (int j = 0; j < 8; j++)
                mma_f16(o[j], pa, vf[j]);
        }
    }

    // ---- epilogue: normalize, fp16 out, concat layout ----
    float inv0 = 1.f / l0, inv1 = 1.f / l1;
    int r0 = t0 + 16 * warp + gid;
#pragma unroll
    for (int j = 0; j < 8; j++) {
        int cI = h * DHd + 8 * j + 2 * tid4;
        __half2 v0 = __floats2half2_rn(o[j][0] * inv0, o[j][1] * inv0);
        __half2 v1 = __floats2half2_rn(o[j][2] * inv1, o[j][3] * inv1);
        *(__half2*)&outp[(size_t)(b * Tt + r0) * Cc + cI]     = v0;
        *(__half2*)&outp[(size_t)(b * Tt + r0 + 8) * Cc + cI] = v1;
    }
}

// ---------------------------------------------------------------------------
// Launch
// ---------------------------------------------------------------------------
extern "C" void kernel_launch(void* const* d_in, const int* in_sizes, int n_in,
                              void* d_out, int out_size) {
    const float* x      = (const float*)d_in[0];
    const float* Wq     = (const float*)d_in[1];
    const float* Wk     = (const float*)d_in[2];
    const float* Wv     = (const float*)d_in[3];
    const float* Wo     = (const float*)d_in[4];
    const float* bo     = (const float*)d_in[5];
    const float* W1     = (const float*)d_in[6];
    const float* b1     = (const float*)d_in[7];
    const float* W2     = (const float*)d_in[8];
    const float* b2     = (const float*)d_in[9];
    const float* gamma1 = (const float*)d_in[10];
    const float* beta1  = (const float*)d_in[11];
    const float* gamma2 = (const float*)d_in[12];
    const float* beta2  = (const float*)d_in[13];
    float* out = (float*)d_out;

    __half *p_x1, *p_qkv, *p_vT, *p_attn, *p_x2, *p_h, *p_wqkv, *p_wo, *p_w1, *p_w2;
    float *p_y;
    cudaGetSymbolAddress((void**)&p_x1,   g_x1);
    cudaGetSymbolAddress((void**)&p_qkv,  g_qkv);
    cudaGetSymbolAddress((void**)&p_vT,   g_vT);
    cudaGetSymbolAddress((void**)&p_attn, g_attn);
    cudaGetSymbolAddress((void**)&p_y,    g_y);
    cudaGetSymbolAddress((void**)&p_x2,   g_x2);
    cudaGetSymbolAddress((void**)&p_h,    g_h);
    cudaGetSymbolAddress((void**)&p_wqkv, g_wqkv);
    cudaGetSymbolAddress((void**)&p_wo,   g_wo);
    cudaGetSymbolAddress((void**)&p_w1,   g_w1);
    cudaGetSymbolAddress((void**)&p_w2,   g_w2);

    cudaFuncSetAttribute(gemm_f16_kernel<false, false, false, false, true>,
                         cudaFuncAttributeMaxDynamicSharedMemorySize, GEMM_SMEM);
    cudaFuncSetAttribute(gemm_f16_kernel<true, false, true, false, false>,
                         cudaFuncAttributeMaxDynamicSharedMemorySize, GEMM_SMEM);
    cudaFuncSetAttribute(gemm_f16_kernel<true, true, false, false, true>,
                         cudaFuncAttributeMaxDynamicSharedMemorySize, GEMM_SMEM);
    cudaFuncSetAttribute(attn_f16_kernel,
                         cudaFuncAttributeMaxDynamicSharedMemorySize, ATT_SMEM);

    dim3 tb(32, 8);

    // 0) weight prep: transpose to [N][K] fp16 (ATT_SCALE folded into Wq)
    pack_qkv_t_kernel<<<dim3(Cc / 32, DHd / 32, 48), tb>>>(Wq, Wk, Wv);
    transpose_h_kernel<<<dim3(Cc / 32, Cc / 32), tb>>>(Wo, p_wo, Cc, Cc);
    transpose_h_kernel<<<dim3(FFN_N / 32, Cc / 32), tb>>>(W1, p_w1, Cc, FFN_N);
    transpose_h_kernel<<<dim3(Cc / 32, FFN_N / 32), tb>>>(W2, p_w2, FFN_N, Cc);

    // 1) LN1 -> fp16
    {
        dim3 grid(Cc / 32, Bb), block(32, 8);
        ln_axis1_kernel<<<grid, block>>>(x, gamma1, beta1, p_x1);
    }

    // 2) fused QKV GEMM -> fp16 qkv
    {
        dim3 grid(QKV_N / 128, Mrows / 128);
        gemm_f16_kernel<false, false, false, false, true><<<grid, 256, GEMM_SMEM>>>(
            p_x1, p_wqkv, nullptr, nullptr, p_qkv, Mrows, QKV_N, Cc);
    }

    // 2b) V transpose -> g_vT [b][h][d][T]
    transpose_v_kernel<<<dim3(Tt / 32, DHd / 32, Bb * Hh), tb>>>(p_qkv, p_vT);

    // 3) causal flash attention (fp16 mma) -> fp16 out
    {
        dim3 grid(Tt / 64, Hh, Bb);
        attn_f16_kernel<<<grid, 128, ATT_SMEM>>>(p_qkv, p_vT, p_attn);
    }

    // 4) output projection + bias + residual -> y fp32
    {
        dim3 grid(Cc / 128, Mrows / 128);
        gemm_f16_kernel<true, false, true, false, false><<<grid, 256, GEMM_SMEM>>>(
            p_attn, p_wo, bo, x, p_y, Mrows, Cc, Cc);
    }

    // 5) LN2 -> fp16
    {
        dim3 grid(Cc / 32, Bb), block(32, 8);
        ln_axis1_kernel<<<grid, block>>>(p_y, gamma2, beta2, p_x2);
    }

    // 6) FFN1: h = relu(x2 @ W1 + b1) -> fp16
    {
        dim3 grid(FFN_N / 128, Mrows / 128);
        gemm_f16_kernel<true, true, false, false, true><<<grid, 256, GEMM_SMEM>>>(
            p_x2, p_w1, b1, nullptr, p_h, Mrows, FFN_N, Cc);
    }

    // 7) FFN2: out = y + h @ W2 + b2 -> fp32
    {
        dim3 grid(Cc / 128, Mrows / 128);
        gemm_f16_kernel<true, false, true, false, false><<<grid, 256, GEMM_SMEM>>>(
            p_h, p_w2, b2, p_y, out, Mrows, Cc, FFN_N);
    }
}

// round 9
// speedup vs baseline: 2.1581x; 1.2338x over previous
#include <cuda_runtime.h>
#include <cuda_fp16.h>
#include <math.h>
#include <stdint.h>

// Problem constants
#define Bb   2
#define Tt   2048
#define Cc   1024
#define Hh   16
#define DHd  64
#define Mrows (Bb * Tt)          // 4096
#define QKV_N (3 * Cc)           // 3072
#define FFN_N (4 * Cc)           // 4096
#define ATT_SCALE 0.03125f       // C^-0.5 = 1/32
#define LN_EPS 1e-5f

// ---------------------------------------------------------------------------
// Scratch (static device allocations; no cudaMalloc allowed)
// ---------------------------------------------------------------------------
__device__ __half g_x1  [Mrows * Cc];
__device__ __half g_qkv [Mrows * QKV_N];
__device__ __half g_vT  [Bb * Hh * DHd * Tt];
__device__ __half g_attn[Mrows * Cc];
__device__ float  g_y   [Mrows * Cc];
__device__ __half g_x2  [Mrows * Cc];
__device__ __half g_h   [Mrows * FFN_N];
__device__ __half g_wqkv[QKV_N * Cc];
__device__ __half g_wo  [Cc * Cc];
__device__ __half g_w1  [FFN_N * Cc];
__device__ __half g_w2  [Cc * FFN_N];

// ---------------------------------------------------------------------------
// Helpers
// ---------------------------------------------------------------------------
__device__ __forceinline__ void cp_async16(void* smem, const void* gmem) {
    unsigned saddr = (unsigned)__cvta_generic_to_shared(smem);
    asm volatile("cp.async.cg.shared.global [%0], [%1], 16;\n"
                 :: "r"(saddr), "l"(gmem));
}
__device__ __forceinline__ void cp_async_commit() {
    asm volatile("cp.async.commit_group;\n" ::: "memory");
}
__device__ __forceinline__ void cp_async_wait0() {
    asm volatile("cp.async.wait_group 0;\n" ::: "memory");
}
__device__ __forceinline__ void cp_async_wait1() {
    asm volatile("cp.async.wait_group 1;\n" ::: "memory");
}

// fp16 mma: m16n8k16, fp32 accum
__device__ __forceinline__ void mma_f16(float c[4],
                                        const uint32_t a[4],
                                        const uint32_t b[2]) {
    asm volatile(
        "mma.sync.aligned.m16n8k16.row.col.f32.f16.f16.f32 "
        "{%0,%1,%2,%3}, {%4,%5,%6,%7}, {%8,%9}, {%0,%1,%2,%3};\n"
        : "+f"(c[0]), "+f"(c[1]), "+f"(c[2]), "+f"(c[3])
        : "r"(a[0]), "r"(a[1]), "r"(a[2]), "r"(a[3]),
          "r"(b[0]), "r"(b[1]));
}
__device__ __forceinline__ uint32_t pack_h2(float a, float b) {
    __half2 h = __floats2half2_rn(a, b);
    return *(uint32_t*)&h;
}
__device__ __forceinline__ void ldsm4(uint32_t r[4], uint32_t saddr) {
    asm volatile("ldmatrix.sync.aligned.m8n8.x4.shared.b16 {%0,%1,%2,%3}, [%4];"
                 : "=r"(r[0]), "=r"(r[1]), "=r"(r[2]), "=r"(r[3])
                 : "r"(saddr));
}

// ---------------------------------------------------------------------------
// Weight prep
// ---------------------------------------------------------------------------
__global__ __launch_bounds__(256)
void transpose_h_kernel(const float* __restrict__ in,
                        __half* __restrict__ out, int R, int Cn) {
    __shared__ float t[32][33];
    int c0 = blockIdx.x * 32, r0 = blockIdx.y * 32;
    int x = threadIdx.x, y = threadIdx.y;
#pragma unroll
    for (int i = 0; i < 32; i += 8)
        t[y + i][x] = in[(size_t)(r0 + y + i) * Cn + c0 + x];
    __syncthreads();
#pragma unroll
    for (int i = 0; i < 32; i += 8)
        out[(size_t)(c0 + y + i) * R + r0 + x] = __float2half(t[x][y + i]);
}

// pack Wq/Wk/Wv [H,C,DH] -> g_wqkv [3C][C] fp16 (transposed), ATT_SCALE in Wq
__global__ __launch_bounds__(256)
void pack_qkv_t_kernel(const float* __restrict__ Wq,
                       const float* __restrict__ Wk,
                       const float* __restrict__ Wv) {
    __shared__ float t[32][33];
    int c0 = blockIdx.x * 32, d0 = blockIdx.y * 32;
    int z = blockIdx.z;
    int sel = z >> 4, h = z & 15;
    const float* W = (sel == 0) ? Wq : (sel == 1) ? Wk : Wv;
    float scl = (sel == 0) ? ATT_SCALE : 1.0f;
    int x = threadIdx.x, y = threadIdx.y;
#pragma unroll
    for (int i = 0; i < 32; i += 8)
        t[y + i][x] = W[(size_t)(h * Cc + c0 + y + i) * DHd + d0 + x];
    __syncthreads();
#pragma unroll
    for (int i = 0; i < 32; i += 8)
        g_wqkv[(size_t)(sel * Cc + h * DHd + d0 + y + i) * Cc + c0 + x] =
            __float2half(t[x][y + i] * scl);
}

// V slice of qkv -> g_vT [(b*Hh+h)*64 + d][t]
__global__ __launch_bounds__(256)
void transpose_v_kernel(const __half* __restrict__ qkv,
                        __half* __restrict__ vT) {
    __shared__ __half t[32][33];
    int t0 = blockIdx.x * 32, d0 = blockIdx.y * 32;
    int z = blockIdx.z;
    int b = z >> 4, h = z & 15;
    int x = threadIdx.x, y = threadIdx.y;
#pragma unroll
    for (int i = 0; i < 32; i += 8)
        t[y + i][x] = qkv[(size_t)(b * Tt + t0 + y + i) * QKV_N
                          + 2 * Cc + h * DHd + d0 + x];
    __syncthreads();
#pragma unroll
    for (int i = 0; i < 32; i += 8)
        vT[(size_t)((b * Hh + h) * DHd + d0 + y + i) * Tt + t0 + x] = t[x][y + i];
}

// ---------------------------------------------------------------------------
// LayerNorm over axis 1 (TIME), unbiased variance. fp16 out.
// 1024 threads/block (32 c x 32 t) for occupancy.
// ---------------------------------------------------------------------------
__global__ __launch_bounds__(1024)
void ln_axis1_kernel(const float* __restrict__ x,
                     const float* __restrict__ gamma,
                     const float* __restrict__ beta,
                     __half* __restrict__ out) {
    int b  = blockIdx.y;
    int tx = threadIdx.x, ty = threadIdx.y;
    int c  = blockIdx.x * 32 + tx;
    const float* xp = x + (size_t)b * Tt * Cc + c;

    float s = 0.f, s2 = 0.f;
    for (int t = ty; t < Tt; t += 32) {
        float v = xp[(size_t)t * Cc];
        s += v; s2 += v * v;
    }
    __shared__ float ss[32][32], sq[32][32];
    __shared__ float smean[32], srstd[32];
    ss[ty][tx] = s; sq[ty][tx] = s2;
    __syncthreads();
    if (ty == 0) {
        float S = 0.f, S2 = 0.f;
#pragma unroll
        for (int k = 0; k < 32; k++) { S += ss[k][tx]; S2 += sq[k][tx]; }
        float mean = S / (float)Tt;
        float var  = (S2 - (float)Tt * mean * mean) / (float)(Tt - 1);
        smean[tx] = mean;
        srstd[tx] = rsqrtf(var + LN_EPS);
    }
    __syncthreads();
    float mean = smean[tx], rstd = srstd[tx];
    float g = gamma[c], be = beta[c];
    __half* op = out + (size_t)b * Tt * Cc + c;
    for (int t = ty; t < Tt; t += 32) {
        op[(size_t)t * Cc] = __float2half(g * (xp[(size_t)t * Cc] - mean) * rstd + be);
    }
}

// ---------------------------------------------------------------------------
// FP16 mma.sync GEMM with ldmatrix fragment loads.
// CTA 128x128, BK=32, 256 thr = 8 warps (4m x 2n), warp tile 32x64.
// 3-stage cp.async, 2 CTAs/SM. A fp16 [M][K]; Bt fp16 [N][K].
// ---------------------------------------------------------------------------
#define HSTR 40
#define TILE_H (128 * HSTR)
#define STG_H  (2 * TILE_H)
#define NSTG 3
#define GEMM_SMEM (NSTG * STG_H * 2)

template<bool BIAS, bool RELU, bool RES, bool OUTH>
__global__ __launch_bounds__(256, 2)
void gemm_f16_kernel(const __half* __restrict__ A,
                     const __half* __restrict__ Bt,
                     const float* __restrict__ bias,
                     const float* __restrict__ res,
                     void* __restrict__ CoutV,
                     int M, int N, int K) {
    extern __shared__ __half smh[];

    const int tid  = threadIdx.x;
    const int lane = tid & 31;
    const int warp = tid >> 5;
    const int wm   = warp >> 1;
    const int wn   = warp & 1;
    const int gid  = lane >> 2;
    const int tid4 = lane & 3;

    // ldmatrix per-lane offsets
    const int lrow = lane & 7;
    const int q    = lane >> 3;
    const int arow = (q & 1) * 8 + lrow;     // A row offset within 16-row block
    const int akof = (q >> 1) * 8;           // A k offset
    const int brow = (q >> 1) * 8 + lrow;    // B n offset within 16-n pair
    const int bkof = (q & 1) * 8;            // B k offset

    const int row0 = blockIdx.y * 128;
    const int col0 = blockIdx.x * 128;
    const int nIter = K >> 5;

    const uint32_t sm_u = (uint32_t)__cvta_generic_to_shared(smh);

    float acc[2][8][4];
#pragma unroll
    for (int i = 0; i < 2; i++)
#pragma unroll
        for (int j = 0; j < 8; j++)
#pragma unroll
            for (int qq = 0; qq < 4; qq++) acc[i][j][qq] = 0.f;

    auto load_stage = [&](int s, int kc) {
        __half* as = smh + s * STG_H;
        __half* bs = as + TILE_H;
        const __half* ap = A  + (size_t)row0 * K + kc * 32;
        const __half* bp = Bt + (size_t)col0 * K + kc * 32;
#pragma unroll
        for (int qq = 0; qq < 2; qq++) {
            int id = tid + 256 * qq;
            int r = id >> 2, c8 = (id & 3) << 3;
            cp_async16(&as[r * HSTR + c8], ap + (size_t)r * K + c8);
        }
#pragma unroll
        for (int qq = 0; qq < 2; qq++) {
            int id = tid + 256 * qq;
            int r = id >> 2, c8 = (id & 3) << 3;
            cp_async16(&bs[r * HSTR + c8], bp + (size_t)r * K + c8);
        }
        cp_async_commit();
    };

    load_stage(0, 0);
    load_stage(1, 1);

    for (int it = 0; it < nIter; ++it) {
        cp_async_wait1();
        __syncthreads();

        if (it + 2 < nIter) load_stage((it + 2) % NSTG, it + 2);
        else                cp_async_commit();

        const int s = it % NSTG;
        const uint32_t as_u = sm_u + (s * STG_H) * 2;
        const uint32_t bs_u = as_u + TILE_H * 2;

#pragma unroll
        for (int ks = 0; ks < 2; ks++) {
            const int k0 = ks * 16;
            uint32_t af[2][4];
#pragma unroll
            for (int i = 0; i < 2; i++)
                ldsm4(af[i], as_u + ((wm * 32 + i * 16 + arow) * HSTR
                                     + k0 + akof) * 2);
            uint32_t bf[8][2];
#pragma unroll
            for (int jp = 0; jp < 4; jp++) {
                uint32_t t4[4];
                ldsm4(t4, bs_u + ((wn * 64 + 16 * jp + brow) * HSTR
                                  + k0 + bkof) * 2);
                bf[2 * jp][0]     = t4[0];
                bf[2 * jp][1]     = t4[1];
                bf[2 * jp + 1][0] = t4[2];
                bf[2 * jp + 1][1] = t4[3];
            }
#pragma unroll
            for (int i = 0; i < 2; i++)
#pragma unroll
                for (int j = 0; j < 8; j++)
                    mma_f16(acc[i][j], af[i], bf[j]);
        }
    }

    float*  Cf = (float*)CoutV;
    __half* Ch = (__half*)CoutV;
#pragma unroll
    for (int i = 0; i < 2; i++) {
#pragma unroll
        for (int hr = 0; hr < 2; hr++) {
            int r = row0 + wm * 32 + i * 16 + hr * 8 + gid;
#pragma unroll
            for (int j = 0; j < 8; j++) {
                int cI = col0 + wn * 64 + j * 8 + 2 * tid4;
                float v0 = acc[i][j][hr * 2];
                float v1 = acc[i][j][hr * 2 + 1];
                if (BIAS) {
                    float2 bi = *(const float2*)&bias[cI];
                    v0 += bi.x; v1 += bi.y;
                }
                if (RES) {
                    float2 rv = *(const float2*)&res[(size_t)r * N + cI];
                    v0 += rv.x; v1 += rv.y;
                }
                if (RELU) { v0 = fmaxf(v0, 0.f); v1 = fmaxf(v1, 0.f); }
                if (OUTH) {
                    *(__half2*)&Ch[(size_t)r * N + cI] = __floats2half2_rn(v0, v1);
                } else {
                    *(float2*)&Cf[(size_t)r * N + cI] = make_float2(v0, v1);
                }
            }
        }
    }
}

// ---------------------------------------------------------------------------
// Causal flash attention, fp16 mma + ldmatrix, register-direct P.
// ---------------------------------------------------------------------------
#define AST 72
#define ATT_SMEM ((64 + 128 + 128) * AST * 2)

__global__ __launch_bounds__(128, 2)
void attn_f16_kernel(const __half* __restrict__ qkv,
                     const __half* __restrict__ vT,
                     __half* __restrict__ outp) {
    extern __shared__ __half sha[];
    __half* Qs = sha;                   // [64][AST]
    __half* Ks = Qs + 64 * AST;         // [2][64][AST]
    __half* Vs = Ks + 2 * 64 * AST;     // [2][64][AST]  (rows = d, cols = s)

    const int qt = blockIdx.x, h = blockIdx.y, b = blockIdx.z;
    const int t0 = qt * 64;
    const int tid  = threadIdx.x;
    const int lane = tid & 31;
    const int warp = tid >> 5;
    const int gid  = lane >> 2;
    const int tid4 = lane & 3;
    const unsigned FULL = 0xffffffffu;

    const int lrow = lane & 7;
    const int q    = lane >> 3;
    const int arow = (q & 1) * 8 + lrow;
    const int akof = (q >> 1) * 8;
    const int brow = (q >> 1) * 8 + lrow;
    const int bkof = (q & 1) * 8;

    const uint32_t sm_u = (uint32_t)__cvta_generic_to_shared(sha);
    const uint32_t Qs_u = sm_u;
    const uint32_t Ks_u = sm_u + 64 * AST * 2;
    const uint32_t Vs_u = Ks_u + 2 * 64 * AST * 2;

    const __half* qb = qkv + (size_t)(b * Tt) * QKV_N + h * DHd;
    const __half* kb = qkv + (size_t)(b * Tt) * QKV_N + Cc + h * DHd;
    const __half* vb = vT + (size_t)((b * Hh + h) * DHd) * Tt;

#pragma unroll
    for (int qq = 0; qq < 4; qq++) {
        int id  = tid + 128 * qq;
        int row = id >> 3;
        int c8  = (id & 7) * 8;
        cp_async16(&Qs[row * AST + c8], qb + (size_t)(t0 + row) * QKV_N + c8);
        cp_async16(&Ks[row * AST + c8], kb + (size_t)row * QKV_N + c8);
        cp_async16(&Vs[row * AST + c8], vb + (size_t)row * Tt + c8);
    }
    cp_async_commit();
    cp_async_wait0();
    __syncthreads();

    // Q fragments register-resident: one ldmatrix.x4 per k-step
    uint32_t qa[4][4];
#pragma unroll
    for (int ks = 0; ks < 4; ks++)
        ldsm4(qa[ks], Qs_u + ((16 * warp + arow) * AST + 16 * ks + akof) * 2);

    float m0 = -1e30f, m1 = -1e30f, l0 = 0.f, l1 = 0.f;
    float o[8][4];
#pragma unroll
    for (int j = 0; j < 8; j++)
#pragma unroll
        for (int qq = 0; qq < 4; qq++) o[j][qq] = 0.f;

    const int nt = qt + 1;
    for (int it = 0; it < nt; ++it) {
        const int buf = it & 1;
        const uint32_t Kb_u = Ks_u + buf * 64 * AST * 2;
        const uint32_t Vb_u = Vs_u + buf * 64 * AST * 2;

        cp_async_wait0();
        __syncthreads();

        if (it + 1 < nt) {
            const int s0 = (it + 1) * 64;
            __half* Kn = Ks + (buf ^ 1) * 64 * AST;
            __half* Vn = Vs + (buf ^ 1) * 64 * AST;
#pragma unroll
            for (int qq = 0; qq < 4; qq++) {
                int id  = tid + 128 * qq;
                int row = id >> 3;
                int c8  = (id & 7) * 8;
                cp_async16(&Kn[row * AST + c8],
                           kb + (size_t)(s0 + row) * QKV_N + c8);
                cp_async16(&Vn[row * AST + c8],
                           vb + (size_t)row * Tt + s0 + c8);
            }
            cp_async_commit();
        }

        // ---- S = Q K^T ----
        float sc[8][4];
#pragma unroll
        for (int j = 0; j < 8; j++)
#pragma unroll
            for (int qq = 0; qq < 4; qq++) sc[j][qq] = 0.f;
#pragma unroll
        for (int ks = 0; ks < 4; ks++) {
            uint32_t kf[8][2];
#pragma unroll
            for (int jp = 0; jp < 4; jp++) {
                uint32_t t4[4];
                ldsm4(t4, Kb_u + ((16 * jp + brow) * AST + 16 * ks + bkof) * 2);
                kf[2 * jp][0]     = t4[0];
                kf[2 * jp][1]     = t4[1];
                kf[2 * jp + 1][0] = t4[2];
                kf[2 * jp + 1][1] = t4[3];
            }
#pragma unroll
            for (int j = 0; j < 8; j++)
                mma_f16(sc[j], qa[ks], kf[j]);
        }

        if (it == qt) {
            int r0 = 16 * warp + gid;
#pragma unroll
            for (int j = 0; j < 8; j++) {
                int c0 = 8 * j + 2 * tid4;
                if (c0     > r0)     sc[j][0] = -1e30f;
                if (c0 + 1 > r0)     sc[j][1] = -1e30f;
                if (c0     > r0 + 8) sc[j][2] = -1e30f;
                if (c0 + 1 > r0 + 8) sc[j][3] = -1e30f;
            }
        }

        // ---- online softmax ----
        float mx0 = -1e30f, mx1 = -1e30f;
#pragma unroll
        for (int j = 0; j < 8; j++) {
            mx0 = fmaxf(mx0, fmaxf(sc[j][0], sc[j][1]));
            mx1 = fmaxf(mx1, fmaxf(sc[j][2], sc[j][3]));
        }
        mx0 = fmaxf(mx0, __shfl_xor_sync(FULL, mx0, 1));
        mx0 = fmaxf(mx0, __shfl_xor_sync(FULL, mx0, 2));
        mx1 = fmaxf(mx1, __shfl_xor_sync(FULL, mx1, 1));
        mx1 = fmaxf(mx1, __shfl_xor_sync(FULL, mx1, 2));
        float mn0 = fmaxf(m0, mx0), mn1 = fmaxf(m1, mx1);
        float sum0 = 0.f, sum1 = 0.f;
#pragma unroll
        for (int j = 0; j < 8; j++) {
            sc[j][0] = __expf(sc[j][0] - mn0);
            sc[j][1] = __expf(sc[j][1] - mn0);
            sc[j][2] = __expf(sc[j][2] - mn1);
            sc[j][3] = __expf(sc[j][3] - mn1);
            sum0 += sc[j][0] + sc[j][1];
            sum1 += sc[j][2] + sc[j][3];
        }
        sum0 += __shfl_xor_sync(FULL, sum0, 1);
        sum0 += __shfl_xor_sync(FULL, sum0, 2);
        sum1 += __shfl_xor_sync(FULL, sum1, 1);
        sum1 += __shfl_xor_sync(FULL, sum1, 2);
        float c0 = __expf(m0 - mn0), c1 = __expf(m1 - mn1);
        l0 = l0 * c0 + sum0;
        l1 = l1 * c1 + sum1;
        m0 = mn0; m1 = mn1;
#pragma unroll
        for (int j = 0; j < 8; j++) {
            o[j][0] *= c0; o[j][1] *= c0;
            o[j][2] *= c1; o[j][3] *= c1;
        }

        // ---- O += P V : P packs directly from sc registers ----
#pragma unroll
        for (int ks = 0; ks < 4; ks++) {
            uint32_t pa[4];
            pa[0] = pack_h2(sc[2 * ks][0],     sc[2 * ks][1]);
            pa[1] = pack_h2(sc[2 * ks][2],     sc[2 * ks][3]);
            pa[2] = pack_h2(sc[2 * ks + 1][0], sc[2 * ks + 1][1]);
            pa[3] = pack_h2(sc[2 * ks + 1][2], sc[2 * ks + 1][3]);
            uint32_t vf[8][2];
#pragma unroll
            for (int jp = 0; jp < 4; jp++) {
                uint32_t t4[4];
                ldsm4(t4, Vb_u + ((16 * jp + brow) * AST + 16 * ks + bkof) * 2);
                vf[2 * jp][0]     = t4[0];
                vf[2 * jp][1]     = t4[1];
                vf[2 * jp + 1][0] = t4[2];
                vf[2 * jp + 1][1] = t4[3];
            }
#pragma unroll
            for (int j = 0; j < 8; j++)
                mma_f16(o[j], pa, vf[j]);
        }
    }

    float inv0 = 1.f / l0, inv1 = 1.f / l1;
    int r0 = t0 + 16 * warp + gid;
#pragma unroll
    for (int j = 0; j < 8; j++) {
        int cI = h * DHd + 8 * j + 2 * tid4;
        __half2 v0 = __floats2half2_rn(o[j][0] * inv0, o[j][1] * inv0);
        __half2 v1 = __floats2half2_rn(o[j][2] * inv1, o[j][3] * inv1);
        *(__half2*)&outp[(size_t)(b * Tt + r0) * Cc + cI]     = v0;
        *(__half2*)&outp[(size_t)(b * Tt + r0 + 8) * Cc + cI] = v1;
    }
}

// ---------------------------------------------------------------------------
// Launch
// ---------------------------------------------------------------------------
extern "C" void kernel_launch(void* const* d_in, const int* in_sizes, int n_in,
                              void* d_out, int out_size) {
    const float* x      = (const float*)d_in[0];
    const float* Wq     = (const float*)d_in[1];
    const float* Wk     = (const float*)d_in[2];
    const float* Wv     = (const float*)d_in[3];
    const float* Wo     = (const float*)d_in[4];
    const float* bo     = (const float*)d_in[5];
    const float* W1     = (const float*)d_in[6];
    const float* b1     = (const float*)d_in[7];
    const float* W2     = (const float*)d_in[8];
    const float* b2     = (const float*)d_in[9];
    const float* gamma1 = (const float*)d_in[10];
    const float* beta1  = (const float*)d_in[11];
    const float* gamma2 = (const float*)d_in[12];
    const float* beta2  = (const float*)d_in[13];
    float* out = (float*)d_out;

    __half *p_x1, *p_qkv, *p_vT, *p_attn, *p_x2, *p_h, *p_wqkv, *p_wo, *p_w1, *p_w2;
    float *p_y;
    cudaGetSymbolAddress((void**)&p_x1,   g_x1);
    cudaGetSymbolAddress((void**)&p_qkv,  g_qkv);
    cudaGetSymbolAddress((void**)&p_vT,   g_vT);
    cudaGetSymbolAddress((void**)&p_attn, g_attn);
    cudaGetSymbolAddress((void**)&p_y,    g_y);
    cudaGetSymbolAddress((void**)&p_x2,   g_x2);
    cudaGetSymbolAddress((void**)&p_h,    g_h);
    cudaGetSymbolAddress((void**)&p_wqkv, g_wqkv);
    cudaGetSymbolAddress((void**)&p_wo,   g_wo);
    cudaGetSymbolAddress((void**)&p_w1,   g_w1);
    cudaGetSymbolAddress((void**)&p_w2,   g_w2);

    cudaFuncSetAttribute(gemm_f16_kernel<false, false, false, true>,
                         cudaFuncAttributeMaxDynamicSharedMemorySize, GEMM_SMEM);
    cudaFuncSetAttribute(gemm_f16_kernel<true, false, true, false>,
                         cudaFuncAttributeMaxDynamicSharedMemorySize, GEMM_SMEM);
    cudaFuncSetAttribute(gemm_f16_kernel<true, true, false, true>,
                         cudaFuncAttributeMaxDynamicSharedMemorySize, GEMM_SMEM);
    cudaFuncSetAttribute(attn_f16_kernel,
                         cudaFuncAttributeMaxDynamicSharedMemorySize, ATT_SMEM);

    dim3 tb(32, 8);

    // 0) weight prep
    pack_qkv_t_kernel<<<dim3(Cc / 32, DHd / 32, 48), tb>>>(Wq, Wk, Wv);
    transpose_h_kernel<<<dim3(Cc / 32, Cc / 32), tb>>>(Wo, p_wo, Cc, Cc);
    transpose_h_kernel<<<dim3(FFN_N / 32, Cc / 32), tb>>>(W1, p_w1, Cc, FFN_N);
    transpose_h_kernel<<<dim3(Cc / 32, FFN_N / 32), tb>>>(W2, p_w2, FFN_N, Cc);

    // 1) LN1 -> fp16
    {
        dim3 grid(Cc / 32, Bb), block(32, 32);
        ln_axis1_kernel<<<grid, block>>>(x, gamma1, beta1, p_x1);
    }

    // 2) fused QKV GEMM -> fp16 qkv
    {
        dim3 grid(QKV_N / 128, Mrows / 128);
        gemm_f16_kernel<false, false, false, true><<<grid, 256, GEMM_SMEM>>>(
            p_x1, p_wqkv, nullptr, nullptr, p_qkv, Mrows, QKV_N, Cc);
    }

    // 2b) V transpose
    transpose_v_kernel<<<dim3(Tt / 32, DHd / 32, Bb * Hh), tb>>>(p_qkv, p_vT);

    // 3) attention
    {
        dim3 grid(Tt / 64, Hh, Bb);
        attn_f16_kernel<<<grid, 128, ATT_SMEM>>>(p_qkv, p_vT, p_attn);
    }

    // 4) output projection + bias + residual -> y fp32
    {
        dim3 grid(Cc / 128, Mrows / 128);
        gemm_f16_kernel<true, false, true, false><<<grid, 256, GEMM_SMEM>>>(
            p_attn, p_wo, bo, x, p_y, Mrows, Cc, Cc);
    }

    // 5) LN2 -> fp16
    {
        dim3 grid(Cc / 32, Bb), block(32, 32);
        ln_axis1_kernel<<<grid, block>>>(p_y, gamma2, beta2, p_x2);
    }

    // 6) FFN1: h = relu(x2 @ W1 + b1) -> fp16
    {
        dim3 grid(FFN_N / 128, Mrows / 128);
        gemm_f16_kernel<true, true, false, true><<<grid, 256, GEMM_SMEM>>>(
            p_x2, p_w1, b1, nullptr, p_h, Mrows, FFN_N, Cc);
    }

    // 7) FFN2: out = y + h @ W2 + b2 -> fp32
    {
        dim3 grid(Cc / 128, Mrows / 128);
        gemm_f16_kernel<true, false, true, false><<<grid, 256, GEMM_SMEM>>>(
            p_h, p_w2, b2, p_y, out, Mrows, Cc, FFN_N);
    }
}